// round 6
// baseline (speedup 1.0000x reference)
#include <cuda_runtime.h>
#include <cuda_bf16.h>
#include <cstdint>
#include <math.h>

#define B_  4
#define N_  2048
#define C_  1024
#define H_  16
#define D_  64
#define BH_ (B_ * H_)   // 64
#define BN_ (B_ * N_)   // 8192

// ---------------- scratch (device globals; no allocations allowed) ----------
__device__ float g_qkv[(size_t)BN_ * 3 * C_];            // [b*n][3C]
__device__ __nv_bfloat16 g_xs[(size_t)2 * BN_ * C_];     // hi plane, lo plane
__device__ __nv_bfloat16 g_atts[(size_t)2 * BN_ * C_];
__device__ __nv_bfloat16 g_wqkvs[(size_t)2 * 3 * C_ * C_];
__device__ __nv_bfloat16 g_wprojs[(size_t)2 * C_ * C_];
__device__ __nv_bfloat16 g_qb[(size_t)2 * BH_ * N_ * D_];  // [2][bh][n][d], pre-scaled
__device__ __nv_bfloat16 g_kb[(size_t)2 * BH_ * N_ * D_];  // [2][bh][n][d]
__device__ __nv_bfloat16 g_vb[(size_t)2 * BH_ * D_ * N_];  // [2][bh][d][n]

#define QKP ((size_t)BH_ * N_ * D_)   // plane stride for q/k/v bf16 buffers

// =====================================================================
// helpers (family-portable PTX only: cp.async / ldmatrix / mma.sync)
// =====================================================================
__device__ __forceinline__ uint32_t smem_u32(const void* p) {
    uint32_t a;
    asm("{ .reg .u64 t; cvta.to.shared.u64 t, %1; cvt.u32.u64 %0, t; }"
        : "=r"(a) : "l"(p));
    return a;
}

__device__ __forceinline__ void cpa16(uint32_t s, const void* g) {
    asm volatile("cp.async.cg.shared.global [%0], [%1], 16;"
                 :: "r"(s), "l"(g) : "memory");
}
#define CP_COMMIT()  asm volatile("cp.async.commit_group;" ::: "memory")
#define CP_WAIT(n)   asm volatile("cp.async.wait_group %0;" :: "n"(n) : "memory")

__device__ __forceinline__ void ldm4(uint32_t addr, uint32_t* r) {
    asm volatile("ldmatrix.sync.aligned.m8n8.x4.shared.b16 {%0,%1,%2,%3}, [%4];"
                 : "=r"(r[0]), "=r"(r[1]), "=r"(r[2]), "=r"(r[3]) : "r"(addr));
}

__device__ __forceinline__ void mma_bf16(float* c, const uint32_t* a, const uint32_t* b) {
    asm volatile(
        "mma.sync.aligned.m16n8k16.row.col.f32.bf16.bf16.f32 "
        "{%0,%1,%2,%3}, {%4,%5,%6,%7}, {%8,%9}, {%0,%1,%2,%3};"
        : "+f"(c[0]), "+f"(c[1]), "+f"(c[2]), "+f"(c[3])
        : "r"(a[0]), "r"(a[1]), "r"(a[2]), "r"(a[3]), "r"(b[0]), "r"(b[1]));
}

__device__ __forceinline__ uint32_t pack_bf2(float a, float b) {
    __nv_bfloat162 t = __floats2bfloat162_rn(a, b);
    return *(uint32_t*)&t;
}

// 64-byte-row swizzle (BK=32 tiles): two logical rows per 128B line.
// off(r,c) = (r>>1)*128 + ((((r&1)*4 + c) ^ ((r>>1)&3)) << 4), c in 0..3
__device__ __forceinline__ uint32_t off64(int r, int c) {
    return (uint32_t)(((r >> 1) << 7) + (((((r & 1) << 2) | c) ^ ((r >> 1) & 3)) << 4));
}

// =====================================================================
// fp32 -> (hi, lo) bf16 split planes
// =====================================================================
__global__ void split_kernel(const float* __restrict__ src,
                             __nv_bfloat16* __restrict__ dst, size_t n)
{
    size_t i = ((size_t)blockIdx.x * blockDim.x + threadIdx.x) * 4;
    if (i >= n) return;
    float4 v = *(const float4*)(src + i);
    __nv_bfloat16 h0 = __float2bfloat16(v.x);
    __nv_bfloat16 h1 = __float2bfloat16(v.y);
    __nv_bfloat16 h2 = __float2bfloat16(v.z);
    __nv_bfloat16 h3 = __float2bfloat16(v.w);
    __nv_bfloat162* hp = (__nv_bfloat162*)(dst + i);
    hp[0] = __halves2bfloat162(h0, h1);
    hp[1] = __halves2bfloat162(h2, h3);
    __nv_bfloat162* lp = (__nv_bfloat162*)(dst + n + i);
    lp[0] = __halves2bfloat162(__float2bfloat16(v.x - __bfloat162float(h0)),
                               __float2bfloat16(v.y - __bfloat162float(h1)));
    lp[1] = __halves2bfloat162(__float2bfloat16(v.z - __bfloat162float(h2)),
                               __float2bfloat16(v.w - __bfloat162float(h3)));
}

// =====================================================================
// bf16x3 GEMM, BK=32, 3 stages x 32KB = 96KB, 2 CTAs/SM, 1 barrier/iter.
// stage: Ahi@0 | Alo@8K | Bhi@16K | Blo@24K (each 128 rows x 64B)
// =====================================================================
#define GSTG 32768
#define GSMEM (3 * GSTG)
__global__ __launch_bounds__(256, 2)
void gemm_mma(const __nv_bfloat16* __restrict__ A, size_t planeA,
              const __nv_bfloat16* __restrict__ Bm, size_t planeB,
              float* __restrict__ C, int ldC, int K)
{
    extern __shared__ char smem[];
    const uint32_t sb = smem_u32(smem);
    const int tid  = threadIdx.x;
    const int lane = tid & 31;
    const int wid  = tid >> 5;
    const int m0 = blockIdx.y * 128;
    const int n0 = blockIdx.x * 128;
    const int wm = (wid >> 2) * 64;
    const int wn = (wid & 3) * 32;

    // global->smem: 512 chunks/plane, 2 per thread
    int lrow[2], lc[2];
    uint32_t lsoff[2];
#pragma unroll
    for (int j = 0; j < 2; j++) {
        int idx = tid + 256 * j;          // 0..511
        lrow[j] = idx >> 2;
        lc[j] = idx & 3;
        lsoff[j] = off64(lrow[j], lc[j]);
    }

    // ldmatrix per-lane row constants
    const int j4 = (lane & 1) * 4;        // row parity (same for A and B rows here)
    const int cA = lane >> 4;             // 0/1
    const int cB = (lane >> 3) & 1;       // 0/1
    uint32_t aCR[4]; int aXR[4];
#pragma unroll
    for (int mt = 0; mt < 4; mt++) {
        const int r = wm + mt * 16 + (lane & 15);
        aCR[mt] = (uint32_t)((r >> 1) << 7);
        aXR[mt] = (r >> 1) & 3;
    }
    uint32_t bCR[2]; int bXR[2];
#pragma unroll
    for (int nt = 0; nt < 2; nt++) {
        const int r = wn + nt * 16 + ((lane >> 4) << 3) + (lane & 7);
        bCR[nt] = (uint32_t)((r >> 1) << 7);
        bXR[nt] = (r >> 1) & 3;
    }

    float acc[4][4][4];
#pragma unroll
    for (int i = 0; i < 4; i++)
#pragma unroll
        for (int j = 0; j < 4; j++)
#pragma unroll
            for (int r = 0; r < 4; r++) acc[i][j][r] = 0.f;

    const int KT = K >> 5;   // BK=32

    auto load_stage = [&](int buf, int kt) {
        const uint32_t st = sb + buf * GSTG;
        const int k0 = kt * 32;
#pragma unroll
        for (int j = 0; j < 2; j++) {
            const __nv_bfloat16* ga = A + (size_t)(m0 + lrow[j]) * K + k0 + lc[j] * 8;
            cpa16(st + lsoff[j], ga);
            cpa16(st + 8192 + lsoff[j], ga + planeA);
            const __nv_bfloat16* gb = Bm + (size_t)(n0 + lrow[j]) * K + k0 + lc[j] * 8;
            cpa16(st + 16384 + lsoff[j], gb);
            cpa16(st + 24576 + lsoff[j], gb + planeB);
        }
        CP_COMMIT();
    };

    load_stage(0, 0);
    load_stage(1, 1);

#pragma unroll 1
    for (int kt = 0; kt < KT; kt++) {
        if (kt + 1 < KT) { CP_WAIT(1); } else { CP_WAIT(0); }
        __syncthreads();
        if (kt + 2 < KT) load_stage((kt + 2) % 3, kt + 2);   // stage held kt-1: drained

        const uint32_t st = sb + (kt % 3) * GSTG;
#pragma unroll
        for (int kk = 0; kk < 2; kk++) {
            uint32_t ah[4][4], al[4][4];
            const int ca = kk * 2 + cA;
            const int cb = kk * 2 + cB;
#pragma unroll
            for (int mt = 0; mt < 4; mt++) {
                const uint32_t ad = st + aCR[mt] + (uint32_t)((((j4 + ca) ^ aXR[mt])) << 4);
                ldm4(ad, ah[mt]);
                ldm4(ad + 8192, al[mt]);
            }
#pragma unroll
            for (int nt = 0; nt < 2; nt++) {
                const uint32_t bd = st + 16384 + bCR[nt] +
                                    (uint32_t)((((j4 + cb) ^ bXR[nt])) << 4);
                uint32_t bh[4], bl[4];
                ldm4(bd, bh);
                ldm4(bd + 8192, bl);
#pragma unroll
                for (int h = 0; h < 2; h++) {
                    const int ng = nt * 2 + h;
#pragma unroll
                    for (int mt = 0; mt < 4; mt++) {
                        mma_bf16(acc[mt][ng], ah[mt], &bh[h * 2]);
                        mma_bf16(acc[mt][ng], ah[mt], &bl[h * 2]);
                        mma_bf16(acc[mt][ng], al[mt], &bh[h * 2]);
                    }
                }
            }
        }
    }

    const int g = lane >> 2, tg = lane & 3;
#pragma unroll
    for (int mt = 0; mt < 4; mt++)
#pragma unroll
        for (int ng = 0; ng < 4; ng++) {
            const int row = m0 + wm + mt * 16 + g;
            const int col = n0 + wn + ng * 8 + tg * 2;
            *(float2*)&C[(size_t)row * ldC + col] =
                make_float2(acc[mt][ng][0], acc[mt][ng][1]);
            *(float2*)&C[(size_t)(row + 8) * ldC + col] =
                make_float2(acc[mt][ng][2], acc[mt][ng][3]);
        }
}

// =====================================================================
// Prep: RMSNorm + RoPE -> bf16 hi/lo planes [bh][n][d].
// q pre-scaled by (1/sqrt(D)) * log2(e) so flash can use exp2f.
// =====================================================================
__global__ void prep_kernel(const float* __restrict__ cosd,
                            const float* __restrict__ sind,
                            const float* __restrict__ qg,
                            const float* __restrict__ kg)
{
    const int bn = blockIdx.x;
    const int n  = bn & (N_ - 1);
    const int b  = bn >> 11;
    const int w  = threadIdx.x >> 5;
    const int l  = threadIdx.x & 31;
    const int d0 = l * 2;

    const float* base = g_qkv + (size_t)bn * (3 * C_) + w * D_ + d0;
    float2 q = *(const float2*)(base);
    float2 k = *(const float2*)(base + C_);

    float sq = q.x * q.x + q.y * q.y;
    float sk = k.x * k.x + k.y * k.y;
#pragma unroll
    for (int ofs = 16; ofs >= 1; ofs >>= 1) {
        sq += __shfl_xor_sync(0xffffffffu, sq, ofs);
        sk += __shfl_xor_sync(0xffffffffu, sk, ofs);
    }
    const float rq = rsqrtf(sq * (1.f / 64.f) + 1e-6f);
    const float rk = rsqrtf(sk * (1.f / 64.f) + 1e-6f);

    float2 gq = *(const float2*)(qg + d0);
    float2 gk = *(const float2*)(kg + d0);
    const float qa = q.x * rq * gq.x, qb = q.y * rq * gq.y;
    const float ka = k.x * rk * gk.x, kb = k.y * rk * gk.y;

    const float QS = 0.125f * 1.4426950408889634f;  // 1/sqrt(D) * log2(e)
    float2 c = *(const float2*)(cosd + n * D_ + d0);
    float2 s = *(const float2*)(sind + n * D_ + d0);
    const float qo0 = (qa * c.x - qb * s.x) * QS;
    const float qo1 = (qb * c.y + qa * s.y) * QS;
    const float ko0 = ka * c.x - kb * s.x;
    const float ko1 = kb * c.y + ka * s.y;

    const int bh = b * H_ + w;
    const size_t qi = ((size_t)bh * N_ + n) * D_ + d0;

    __nv_bfloat16 qh0 = __float2bfloat16(qo0), qh1 = __float2bfloat16(qo1);
    *(__nv_bfloat162*)&g_qb[qi] = __halves2bfloat162(qh0, qh1);
    *(__nv_bfloat162*)&g_qb[QKP + qi] =
        __halves2bfloat162(__float2bfloat16(qo0 - __bfloat162float(qh0)),
                           __float2bfloat16(qo1 - __bfloat162float(qh1)));
    __nv_bfloat16 kh0 = __float2bfloat16(ko0), kh1 = __float2bfloat16(ko1);
    *(__nv_bfloat162*)&g_kb[qi] = __halves2bfloat162(kh0, kh1);
    *(__nv_bfloat162*)&g_kb[QKP + qi] =
        __halves2bfloat162(__float2bfloat16(ko0 - __bfloat162float(kh0)),
                           __float2bfloat16(ko1 - __bfloat162float(kh1)));
}

// =====================================================================
// V transpose: g_qkv v-part [b][n][h*64+d] -> g_vb [2][bh][d][n] bf16 hi/lo
// =====================================================================
__global__ void vtrans_kernel()
{
    __shared__ float t[64][65];
    const int bh = blockIdx.x;
    const int n0 = blockIdx.y * 64;
    const int b = bh >> 4, h = bh & 15;
    const int tid = threadIdx.x;

    for (int i = tid; i < 4096; i += 256) {
        const int r = i >> 6, c = i & 63;
        t[c][r] = g_qkv[((size_t)(b * N_ + n0 + r)) * (3 * C_) + 2 * C_ + h * 64 + c];
    }
    __syncthreads();
    for (int i = tid; i < 4096; i += 256) {
        const int d = i >> 6, n = i & 63;
        const float v = t[d][n];
        const __nv_bfloat16 hv = __float2bfloat16(v);
        const size_t oi = ((size_t)bh * D_ + d) * N_ + n0 + n;
        g_vb[oi] = hv;
        g_vb[QKP + oi] = __float2bfloat16(v - __bfloat162float(hv));
    }
}

// =====================================================================
// Flash attention (bf16x3), K-tile = 64 keys, 2 stages x 32KB + Q 32KB
// = 96KB -> 2 CTAs/SM. stage: Khi@0|Klo@8K|Vhi@16K|Vlo@24K (64 rows x 128B)
// =====================================================================
#define FSTG 32768
#define FLASH_SMEM (32768 + 2 * FSTG)

__global__ __launch_bounds__(256, 2)
void flash_mma(__nv_bfloat16* __restrict__ outs)
{
    extern __shared__ char smem[];
    const uint32_t sb = smem_u32(smem);
    const int bh  = blockIdx.y;
    const int q0  = blockIdx.x * 128;
    const int tid = threadIdx.x;
    const int lane = tid & 31;
    const int wid  = tid >> 5;

    const __nv_bfloat16* qbp = g_qb + (size_t)bh * N_ * D_;
    const __nv_bfloat16* kbp = g_kb + (size_t)bh * N_ * D_;
    const __nv_bfloat16* vbp = g_vb + (size_t)bh * D_ * N_;

    // Q: 1024 chunks/plane (128 rows x 8), 4 per thread, 128B-row swizzle
#pragma unroll
    for (int j = 0; j < 4; j++) {
        int idx = tid + 256 * j;
        const int r = idx >> 3, c = idx & 7;
        const uint32_t so = (uint32_t)(r * 128 + ((c ^ (r & 7)) << 4));
        const __nv_bfloat16* gq = qbp + (size_t)(q0 + r) * D_ + c * 8;
        cpa16(sb + so, gq);
        cpa16(sb + 16384 + so, gq + QKP);
    }

    // K/V stage chunks: 512 per plane, 2 per thread
    int lrow[2], lc[2];
    uint32_t lsoff[2];
#pragma unroll
    for (int j = 0; j < 2; j++) {
        int idx = tid + 256 * j;          // 0..511
        lrow[j] = idx >> 3;               // 0..63
        lc[j] = idx & 7;
        lsoff[j] = (uint32_t)(lrow[j] * 128 + ((lc[j] ^ (lrow[j] & 7)) << 4));
    }

    auto load_stage = [&](int buf, int kt) {
        const uint32_t st = sb + 32768 + buf * FSTG;
        const int kc0 = kt * 64;
#pragma unroll
        for (int j = 0; j < 2; j++) {
            const __nv_bfloat16* gk = kbp + (size_t)(kc0 + lrow[j]) * D_ + lc[j] * 8;
            cpa16(st + lsoff[j], gk);
            cpa16(st + 8192 + lsoff[j], gk + QKP);
            const __nv_bfloat16* gv = vbp + (size_t)lrow[j] * N_ + kc0 + lc[j] * 8;
            cpa16(st + 16384 + lsoff[j], gv);
            cpa16(st + 24576 + lsoff[j], gv + QKP);
        }
        CP_COMMIT();
    };

    load_stage(0, 0);   // group 0: Q + stage 0

    const int swz = lane & 7;
    const int cA = lane >> 4;
    const int cB = (lane >> 3) & 1;
    const uint32_t aoff = (uint32_t)((wid * 16 + (lane & 15)) * 128);
    uint32_t boff[4];
#pragma unroll
    for (int nt = 0; nt < 4; nt++)
        boff[nt] = (uint32_t)((nt * 16 + ((lane >> 4) << 3) + (lane & 7)) * 128);

    float oc[8][4];
    float m_r[2], l_r[2];
#pragma unroll
    for (int i = 0; i < 8; i++)
#pragma unroll
        for (int j = 0; j < 4; j++) oc[i][j] = 0.f;
    m_r[0] = m_r[1] = -1e30f;
    l_r[0] = l_r[1] = 0.f;

    const int KTN = N_ / 64;
#pragma unroll 1
    for (int kt = 0; kt < KTN; kt++) {
        CP_WAIT(0);
        __syncthreads();
        if (kt + 1 < KTN) load_stage((kt + 1) & 1, kt + 1);  // stage drained at barrier
        const uint32_t st = sb + 32768 + (kt & 1) * FSTG;

        // ---- S = Q K^T (64 keys), log2 units ----
        float sc[8][4];
#pragma unroll
        for (int i = 0; i < 8; i++)
#pragma unroll
            for (int j = 0; j < 4; j++) sc[i][j] = 0.f;

#pragma unroll
        for (int kk = 0; kk < 4; kk++) {
            const uint32_t swA = (uint32_t)(((kk * 2 + cA) ^ swz) << 4);
            const uint32_t swB = (uint32_t)(((kk * 2 + cB) ^ swz) << 4);
            uint32_t aq[4], aql[4];
            ldm4(sb + aoff + swA, aq);
            ldm4(sb + 16384 + aoff + swA, aql);
#pragma unroll
            for (int nt = 0; nt < 4; nt++) {
                uint32_t kh[4], kl[4];
                ldm4(st + boff[nt] + swB, kh);
                ldm4(st + 8192 + boff[nt] + swB, kl);
#pragma unroll
                for (int h = 0; h < 2; h++) {
                    const int ng = nt * 2 + h;
                    mma_bf16(sc[ng], aq, &kh[h * 2]);
                    mma_bf16(sc[ng], aq, &kl[h * 2]);
                    mma_bf16(sc[ng], aql, &kh[h * 2]);
                }
            }
        }

        // ---- online softmax (exp2) ----
#pragma unroll
        for (int p = 0; p < 2; p++) {
            float mx = -1e30f;
#pragma unroll
            for (int ng = 0; ng < 8; ng++)
                mx = fmaxf(mx, fmaxf(sc[ng][2 * p], sc[ng][2 * p + 1]));
            mx = fmaxf(mx, __shfl_xor_sync(0xffffffffu, mx, 1));
            mx = fmaxf(mx, __shfl_xor_sync(0xffffffffu, mx, 2));
            const float mnew = fmaxf(m_r[p], mx);
            const float f = exp2f(m_r[p] - mnew);
            m_r[p] = mnew;
            float rs = 0.f;
#pragma unroll
            for (int ng = 0; ng < 8; ng++) {
                sc[ng][2 * p]     = exp2f(sc[ng][2 * p] - mnew);
                sc[ng][2 * p + 1] = exp2f(sc[ng][2 * p + 1] - mnew);
                rs += sc[ng][2 * p] + sc[ng][2 * p + 1];
            }
            rs += __shfl_xor_sync(0xffffffffu, rs, 1);
            rs += __shfl_xor_sync(0xffffffffu, rs, 2);
            l_r[p] = l_r[p] * f + rs;
#pragma unroll
            for (int dt = 0; dt < 8; dt++) {
                oc[dt][2 * p] *= f;
                oc[dt][2 * p + 1] *= f;
            }
        }

        // ---- O += P V ----
#pragma unroll
        for (int kk = 0; kk < 4; kk++) {
            uint32_t ph[4], pl[4];
#pragma unroll
            for (int u = 0; u < 2; u++) {
                const int ng = 2 * kk + u;
#pragma unroll
                for (int v = 0; v < 2; v++) {
                    const float p0 = sc[ng][2 * v];
                    const float p1 = sc[ng][2 * v + 1];
                    const __nv_bfloat16 h0 = __float2bfloat16(p0);
                    const __nv_bfloat16 h1 = __float2bfloat16(p1);
                    ph[u * 2 + v] = pack_bf2(__bfloat162float(h0), __bfloat162float(h1));
                    pl[u * 2 + v] = pack_bf2(p0 - __bfloat162float(h0),
                                             p1 - __bfloat162float(h1));
                }
            }
            const uint32_t swV = (uint32_t)(((kk * 2 + cB) ^ swz) << 4);
#pragma unroll
            for (int nt = 0; nt < 4; nt++) {
                uint32_t vh[4], vl[4];
                ldm4(st + 16384 + boff[nt] + swV, vh);
                ldm4(st + 24576 + boff[nt] + swV, vl);
#pragma unroll
                for (int h2 = 0; h2 < 2; h2++) {
                    const int dt = nt * 2 + h2;
                    mma_bf16(oc[dt], ph, &vh[h2 * 2]);
                    mma_bf16(oc[dt], ph, &vl[h2 * 2]);
                    mma_bf16(oc[dt], pl, &vh[h2 * 2]);
                }
            }
        }
    }

    // ---- epilogue: O/l -> bf16 hi/lo planes in (B,N,C) layout ----
    const size_t nx = (size_t)BN_ * C_;
    const int b = bh >> 4, h = bh & 15;
#pragma unroll
    for (int p = 0; p < 2; p++) {
        const int n = q0 + wid * 16 + (lane >> 2) + 8 * p;
        const float inv = 1.f / l_r[p];
#pragma unroll
        for (int dt = 0; dt < 8; dt++) {
            const int d = dt * 8 + 2 * (lane & 3);
            const float v0 = oc[dt][2 * p] * inv;
            const float v1 = oc[dt][2 * p + 1] * inv;
            const __nv_bfloat16 h0 = __float2bfloat16(v0);
            const __nv_bfloat16 h1 = __float2bfloat16(v1);
            const size_t oi = ((size_t)(b * N_ + n)) * C_ + h * D_ + d;
            *(__nv_bfloat162*)&outs[oi] = __halves2bfloat162(h0, h1);
            *(__nv_bfloat162*)&outs[nx + oi] =
                __halves2bfloat162(__float2bfloat16(v0 - __bfloat162float(h0)),
                                   __float2bfloat16(v1 - __bfloat162float(h1)));
        }
    }
}

// =====================================================================
extern "C" void kernel_launch(void* const* d_in, const int* in_sizes, int n_in,
                              void* d_out, int out_size)
{
    const float* x      = (const float*)d_in[0];
    const float* cosd   = (const float*)d_in[1];
    const float* sind   = (const float*)d_in[2];
    const float* w_qkv  = (const float*)d_in[3];
    const float* w_proj = (const float*)d_in[4];
    const float* q_gam  = (const float*)d_in[5];
    const float* k_gam  = (const float*)d_in[6];
    float* out = (float*)d_out;

    float* p_qkv = nullptr;
    __nv_bfloat16 *p_xs = nullptr, *p_atts = nullptr, *p_wqkvs = nullptr, *p_wprojs = nullptr;
    cudaGetSymbolAddress((void**)&p_qkv, g_qkv);
    cudaGetSymbolAddress((void**)&p_xs, g_xs);
    cudaGetSymbolAddress((void**)&p_atts, g_atts);
    cudaGetSymbolAddress((void**)&p_wqkvs, g_wqkvs);
    cudaGetSymbolAddress((void**)&p_wprojs, g_wprojs);

    const size_t n_x = (size_t)BN_ * C_;
    const size_t n_wqkv = (size_t)3 * C_ * C_;
    const size_t n_wproj = (size_t)C_ * C_;

    cudaFuncSetAttribute(gemm_mma,
                         cudaFuncAttributeMaxDynamicSharedMemorySize, GSMEM);
    cudaFuncSetAttribute(flash_mma,
                         cudaFuncAttributeMaxDynamicSharedMemorySize, FLASH_SMEM);

    // 1) split inputs to (hi,lo) bf16 planes
    split_kernel<<<(int)(n_x / 4 / 256), 256>>>(x, p_xs, n_x);
    split_kernel<<<(int)(n_wqkv / 4 / 256), 256>>>(w_qkv, p_wqkvs, n_wqkv);
    split_kernel<<<(int)(n_wproj / 4 / 256), 256>>>(w_proj, p_wprojs, n_wproj);

    // 2) QKV projection (tensor cores)
    gemm_mma<<<dim3(3 * C_ / 128, BN_ / 128), 256, GSMEM>>>(
        p_xs, n_x, p_wqkvs, n_wqkv, p_qkv, 3 * C_, C_);

    // 3) RMSNorm + RoPE -> bf16 planes; V transpose -> bf16 planes
    prep_kernel<<<BN_, 512>>>(cosd, sind, q_gam, k_gam);
    vtrans_kernel<<<dim3(BH_, N_ / 64), 256>>>();

    // 4) flash attention on tensor cores
    flash_mma<<<dim3(N_ / 128, BH_), 256, FLASH_SMEM>>>(p_atts);

    // 5) output projection (tensor cores)
    gemm_mma<<<dim3(C_ / 128, BN_ / 128), 256, GSMEM>>>(
        p_atts, n_x, p_wprojs, n_wproj, out, C_, C_);
}

// round 7
// speedup vs baseline: 2.1221x; 2.1221x over previous
#include <cuda_runtime.h>
#include <cuda_bf16.h>
#include <cuda_fp16.h>
#include <cstdint>
#include <math.h>

#define B_  4
#define N_  2048
#define C_  1024
#define H_  16
#define D_  64
#define BH_ (B_ * H_)   // 64
#define BN_ (B_ * N_)   // 8192

// ---------------- scratch (device globals; no allocations allowed) ----------
__device__ float g_qkv[(size_t)BN_ * 3 * C_];            // [b*n][3C]
__device__ __nv_bfloat16 g_xs[(size_t)2 * BN_ * C_];     // x: bf16 hi/lo
__device__ __nv_bfloat16 g_wqkvs[(size_t)2 * 3 * C_ * C_]; // w_qkv: bf16 hi/lo
__device__ __half g_wprojh[(size_t)C_ * C_];             // w_proj: fp16 (rounded)
__device__ __half g_atth[(size_t)2 * BN_ * C_];          // att: fp16 hi/lo
__device__ __half g_qh[(size_t)2 * BH_ * N_ * D_];       // q: fp16 hi/lo, pre-scaled
__device__ __half g_kh[(size_t)BH_ * N_ * D_];           // k: fp16 (rounded)
__device__ __half g_vh[(size_t)BH_ * D_ * N_];           // v: fp16 (rounded), [bh][d][n]

#define QKP ((size_t)BH_ * N_ * D_)   // plane stride for q hi/lo

// =====================================================================
// helpers (family-portable PTX only: cp.async / ldmatrix / mma.sync)
// =====================================================================
__device__ __forceinline__ uint32_t smem_u32(const void* p) {
    uint32_t a;
    asm("{ .reg .u64 t; cvta.to.shared.u64 t, %1; cvt.u32.u64 %0, t; }"
        : "=r"(a) : "l"(p));
    return a;
}

__device__ __forceinline__ void cpa16(uint32_t s, const void* g) {
    asm volatile("cp.async.cg.shared.global [%0], [%1], 16;"
                 :: "r"(s), "l"(g) : "memory");
}
#define CP_COMMIT()  asm volatile("cp.async.commit_group;" ::: "memory")
#define CP_WAIT(n)   asm volatile("cp.async.wait_group %0;" :: "n"(n) : "memory")

__device__ __forceinline__ void ldm4(uint32_t addr, uint32_t* r) {
    asm volatile("ldmatrix.sync.aligned.m8n8.x4.shared.b16 {%0,%1,%2,%3}, [%4];"
                 : "=r"(r[0]), "=r"(r[1]), "=r"(r[2]), "=r"(r[3]) : "r"(addr));
}

__device__ __forceinline__ void mma_bf16(float* c, const uint32_t* a, const uint32_t* b) {
    asm volatile(
        "mma.sync.aligned.m16n8k16.row.col.f32.bf16.bf16.f32 "
        "{%0,%1,%2,%3}, {%4,%5,%6,%7}, {%8,%9}, {%0,%1,%2,%3};"
        : "+f"(c[0]), "+f"(c[1]), "+f"(c[2]), "+f"(c[3])
        : "r"(a[0]), "r"(a[1]), "r"(a[2]), "r"(a[3]), "r"(b[0]), "r"(b[1]));
}

__device__ __forceinline__ void mma_f16(float* c, const uint32_t* a, const uint32_t* b) {
    asm volatile(
        "mma.sync.aligned.m16n8k16.row.col.f32.f16.f16.f32 "
        "{%0,%1,%2,%3}, {%4,%5,%6,%7}, {%8,%9}, {%0,%1,%2,%3};"
        : "+f"(c[0]), "+f"(c[1]), "+f"(c[2]), "+f"(c[3])
        : "r"(a[0]), "r"(a[1]), "r"(a[2]), "r"(a[3]), "r"(b[0]), "r"(b[1]));
}

__device__ __forceinline__ uint32_t pack_h2(float a, float b) {
    __half2 t = __floats2half2_rn(a, b);
    return *(uint32_t*)&t;
}

// =====================================================================
// fp32 -> (hi, lo) bf16 split planes
// =====================================================================
__global__ void split_kernel(const float* __restrict__ src,
                             __nv_bfloat16* __restrict__ dst, size_t n)
{
    size_t i = ((size_t)blockIdx.x * blockDim.x + threadIdx.x) * 4;
    if (i >= n) return;
    float4 v = *(const float4*)(src + i);
    __nv_bfloat16 h0 = __float2bfloat16(v.x);
    __nv_bfloat16 h1 = __float2bfloat16(v.y);
    __nv_bfloat16 h2 = __float2bfloat16(v.z);
    __nv_bfloat16 h3 = __float2bfloat16(v.w);
    __nv_bfloat162* hp = (__nv_bfloat162*)(dst + i);
    hp[0] = __halves2bfloat162(h0, h1);
    hp[1] = __halves2bfloat162(h2, h3);
    __nv_bfloat162* lp = (__nv_bfloat162*)(dst + n + i);
    lp[0] = __halves2bfloat162(__float2bfloat16(v.x - __bfloat162float(h0)),
                               __float2bfloat16(v.y - __bfloat162float(h1)));
    lp[1] = __halves2bfloat162(__float2bfloat16(v.z - __bfloat162float(h2)),
                               __float2bfloat16(v.w - __bfloat162float(h3)));
}

// fp32 -> fp16 (single rounded plane)
__global__ void splith_kernel(const float* __restrict__ src,
                              __half* __restrict__ dst, size_t n)
{
    size_t i = ((size_t)blockIdx.x * blockDim.x + threadIdx.x) * 4;
    if (i >= n) return;
    float4 v = *(const float4*)(src + i);
    __half2* hp = (__half2*)(dst + i);
    hp[0] = __floats2half2_rn(v.x, v.y);
    hp[1] = __floats2half2_rn(v.z, v.w);
}

// =====================================================================
// bf16x3 GEMM (R5-validated): C = A[M,K]*B[N,K]^T, 3-stage pipeline.
// Used for QKV only.
// =====================================================================
#define STG 65536
#define GSMEM (3 * STG)
__global__ __launch_bounds__(256, 1)
void gemm_mma(const __nv_bfloat16* __restrict__ A, size_t planeA,
              const __nv_bfloat16* __restrict__ Bm, size_t planeB,
              float* __restrict__ C, int ldC, int K)
{
    extern __shared__ char smem[];
    const uint32_t sb = smem_u32(smem);
    const int tid  = threadIdx.x;
    const int lane = tid & 31;
    const int wid  = tid >> 5;
    const int m0 = blockIdx.y * 128;
    const int n0 = blockIdx.x * 128;
    const int wm = (wid >> 2) * 64;
    const int wn = (wid & 3) * 32;

    int lrow[4], lc[4];
    uint32_t lsoff[4];
#pragma unroll
    for (int j = 0; j < 4; j++) {
        int idx = tid + 256 * j;
        lrow[j] = idx >> 3;
        lc[j] = idx & 7;
        lsoff[j] = (uint32_t)(lrow[j] * 128 + ((lc[j] ^ (lrow[j] & 7)) << 4));
    }

    uint32_t arow[4], brow[2];
#pragma unroll
    for (int mt = 0; mt < 4; mt++) arow[mt] = (uint32_t)((wm + mt * 16 + (lane & 15)) * 128);
#pragma unroll
    for (int nt = 0; nt < 2; nt++)
        brow[nt] = (uint32_t)((wn + nt * 16 + ((lane >> 4) << 3) + (lane & 7)) * 128);
    const int swz = lane & 7;
    const int cA = lane >> 4;
    const int cB = (lane >> 3) & 1;

    float acc[4][4][4];
#pragma unroll
    for (int i = 0; i < 4; i++)
#pragma unroll
        for (int j = 0; j < 4; j++)
#pragma unroll
            for (int r = 0; r < 4; r++) acc[i][j][r] = 0.f;

    const int KT = K >> 6;

    auto load_stage = [&](int buf, int kt) {
        const uint32_t st = sb + buf * STG;
        const int k0 = kt * 64;
#pragma unroll
        for (int j = 0; j < 4; j++) {
            const __nv_bfloat16* ga = A + (size_t)(m0 + lrow[j]) * K + k0 + lc[j] * 8;
            cpa16(st + lsoff[j], ga);
            cpa16(st + 16384 + lsoff[j], ga + planeA);
            const __nv_bfloat16* gb = Bm + (size_t)(n0 + lrow[j]) * K + k0 + lc[j] * 8;
            cpa16(st + 32768 + lsoff[j], gb);
            cpa16(st + 49152 + lsoff[j], gb + planeB);
        }
        CP_COMMIT();
    };

    load_stage(0, 0);
    load_stage(1, 1);
    load_stage(2, 2);

#pragma unroll 1
    for (int kt = 0; kt < KT; kt++) {
        if (kt + 2 < KT)      { CP_WAIT(2); }
        else if (kt + 1 < KT) { CP_WAIT(1); }
        else                  { CP_WAIT(0); }
        __syncthreads();

        const uint32_t st = sb + (kt % 3) * STG;
#pragma unroll
        for (int kk = 0; kk < 4; kk++) {
            uint32_t ah[4][4], al[4][4], bh[2][4], bl[2][4];
            const uint32_t swA = (uint32_t)(((kk * 2 + cA) ^ swz) << 4);
            const uint32_t swB = (uint32_t)(((kk * 2 + cB) ^ swz) << 4);
#pragma unroll
            for (int mt = 0; mt < 4; mt++) {
                ldm4(st + arow[mt] + swA, ah[mt]);
                ldm4(st + 16384 + arow[mt] + swA, al[mt]);
            }
#pragma unroll
            for (int nt = 0; nt < 2; nt++) {
                ldm4(st + 32768 + brow[nt] + swB, bh[nt]);
                ldm4(st + 49152 + brow[nt] + swB, bl[nt]);
            }
#pragma unroll
            for (int mt = 0; mt < 4; mt++)
#pragma unroll
                for (int nt = 0; nt < 2; nt++)
#pragma unroll
                    for (int h = 0; h < 2; h++) {
                        const int ng = nt * 2 + h;
                        mma_bf16(acc[mt][ng], ah[mt], &bh[nt][h * 2]);
                        mma_bf16(acc[mt][ng], ah[mt], &bl[nt][h * 2]);
                        mma_bf16(acc[mt][ng], al[mt], &bh[nt][h * 2]);
                    }
        }
        __syncthreads();
        if (kt + 3 < KT) load_stage(kt % 3, kt + 3);
    }

    const int g = lane >> 2, tg = lane & 3;
#pragma unroll
    for (int mt = 0; mt < 4; mt++)
#pragma unroll
        for (int ng = 0; ng < 4; ng++) {
            const int row = m0 + wm + mt * 16 + g;
            const int col = n0 + wn + ng * 8 + tg * 2;
            *(float2*)&C[(size_t)row * ldC + col] =
                make_float2(acc[mt][ng][0], acc[mt][ng][1]);
            *(float2*)&C[(size_t)(row + 8) * ldC + col] =
                make_float2(acc[mt][ng][2], acc[mt][ng][3]);
        }
}

// =====================================================================
// fp16 2-pass GEMM: C = (Ahi+Alo)[M,K] * B[N,K]^T, B pre-rounded fp16.
// stage: Ahi 16K | Alo 16K | B 16K = 48KB; 3 stages = 144KB. (proj)
// =====================================================================
#define STG2 49152
#define GSMEM2 (3 * STG2)
__global__ __launch_bounds__(256, 1)
void gemm2_mma(const __half* __restrict__ A, size_t planeA,
               const __half* __restrict__ Bm,
               float* __restrict__ C, int ldC, int K)
{
    extern __shared__ char smem[];
    const uint32_t sb = smem_u32(smem);
    const int tid  = threadIdx.x;
    const int lane = tid & 31;
    const int wid  = tid >> 5;
    const int m0 = blockIdx.y * 128;
    const int n0 = blockIdx.x * 128;
    const int wm = (wid >> 2) * 64;
    const int wn = (wid & 3) * 32;

    int lrow[4], lc[4];
    uint32_t lsoff[4];
#pragma unroll
    for (int j = 0; j < 4; j++) {
        int idx = tid + 256 * j;
        lrow[j] = idx >> 3;
        lc[j] = idx & 7;
        lsoff[j] = (uint32_t)(lrow[j] * 128 + ((lc[j] ^ (lrow[j] & 7)) << 4));
    }

    uint32_t arow[4], brow[2];
#pragma unroll
    for (int mt = 0; mt < 4; mt++) arow[mt] = (uint32_t)((wm + mt * 16 + (lane & 15)) * 128);
#pragma unroll
    for (int nt = 0; nt < 2; nt++)
        brow[nt] = (uint32_t)((wn + nt * 16 + ((lane >> 4) << 3) + (lane & 7)) * 128);
    const int swz = lane & 7;
    const int cA = lane >> 4;
    const int cB = (lane >> 3) & 1;

    float acc[4][4][4];
#pragma unroll
    for (int i = 0; i < 4; i++)
#pragma unroll
        for (int j = 0; j < 4; j++)
#pragma unroll
            for (int r = 0; r < 4; r++) acc[i][j][r] = 0.f;

    const int KT = K >> 6;

    auto load_stage = [&](int buf, int kt) {
        const uint32_t st = sb + buf * STG2;
        const int k0 = kt * 64;
#pragma unroll
        for (int j = 0; j < 4; j++) {
            const __half* ga = A + (size_t)(m0 + lrow[j]) * K + k0 + lc[j] * 8;
            cpa16(st + lsoff[j], ga);
            cpa16(st + 16384 + lsoff[j], ga + planeA);
            const __half* gb = Bm + (size_t)(n0 + lrow[j]) * K + k0 + lc[j] * 8;
            cpa16(st + 32768 + lsoff[j], gb);
        }
        CP_COMMIT();
    };

    load_stage(0, 0);
    load_stage(1, 1);
    load_stage(2, 2);

#pragma unroll 1
    for (int kt = 0; kt < KT; kt++) {
        if (kt + 2 < KT)      { CP_WAIT(2); }
        else if (kt + 1 < KT) { CP_WAIT(1); }
        else                  { CP_WAIT(0); }
        __syncthreads();

        const uint32_t st = sb + (kt % 3) * STG2;
#pragma unroll
        for (int kk = 0; kk < 4; kk++) {
            uint32_t ah[4][4], al[4][4], bh[2][4];
            const uint32_t swA = (uint32_t)(((kk * 2 + cA) ^ swz) << 4);
            const uint32_t swB = (uint32_t)(((kk * 2 + cB) ^ swz) << 4);
#pragma unroll
            for (int mt = 0; mt < 4; mt++) {
                ldm4(st + arow[mt] + swA, ah[mt]);
                ldm4(st + 16384 + arow[mt] + swA, al[mt]);
            }
#pragma unroll
            for (int nt = 0; nt < 2; nt++)
                ldm4(st + 32768 + brow[nt] + swB, bh[nt]);
#pragma unroll
            for (int mt = 0; mt < 4; mt++)
#pragma unroll
                for (int nt = 0; nt < 2; nt++)
#pragma unroll
                    for (int h = 0; h < 2; h++) {
                        const int ng = nt * 2 + h;
                        mma_f16(acc[mt][ng], ah[mt], &bh[nt][h * 2]);
                        mma_f16(acc[mt][ng], al[mt], &bh[nt][h * 2]);
                    }
        }
        __syncthreads();
        if (kt + 3 < KT) load_stage(kt % 3, kt + 3);
    }

    const int g = lane >> 2, tg = lane & 3;
#pragma unroll
    for (int mt = 0; mt < 4; mt++)
#pragma unroll
        for (int ng = 0; ng < 4; ng++) {
            const int row = m0 + wm + mt * 16 + g;
            const int col = n0 + wn + ng * 8 + tg * 2;
            *(float2*)&C[(size_t)row * ldC + col] =
                make_float2(acc[mt][ng][0], acc[mt][ng][1]);
            *(float2*)&C[(size_t)(row + 8) * ldC + col] =
                make_float2(acc[mt][ng][2], acc[mt][ng][3]);
        }
}

// =====================================================================
// Prep: RMSNorm + RoPE -> q fp16 hi/lo (pre-scaled by log2e/sqrt(D)),
// k fp16 single. [bh][n][d] layout.
// =====================================================================
__global__ void prep_kernel(const float* __restrict__ cosd,
                            const float* __restrict__ sind,
                            const float* __restrict__ qg,
                            const float* __restrict__ kg)
{
    const int bn = blockIdx.x;
    const int n  = bn & (N_ - 1);
    const int b  = bn >> 11;
    const int w  = threadIdx.x >> 5;
    const int l  = threadIdx.x & 31;
    const int d0 = l * 2;

    const float* base = g_qkv + (size_t)bn * (3 * C_) + w * D_ + d0;
    float2 q = *(const float2*)(base);
    float2 k = *(const float2*)(base + C_);

    float sq = q.x * q.x + q.y * q.y;
    float sk = k.x * k.x + k.y * k.y;
#pragma unroll
    for (int ofs = 16; ofs >= 1; ofs >>= 1) {
        sq += __shfl_xor_sync(0xffffffffu, sq, ofs);
        sk += __shfl_xor_sync(0xffffffffu, sk, ofs);
    }
    const float rq = rsqrtf(sq * (1.f / 64.f) + 1e-6f);
    const float rk = rsqrtf(sk * (1.f / 64.f) + 1e-6f);

    float2 gq = *(const float2*)(qg + d0);
    float2 gk = *(const float2*)(kg + d0);
    const float qa = q.x * rq * gq.x, qb = q.y * rq * gq.y;
    const float ka = k.x * rk * gk.x, kb = k.y * rk * gk.y;

    const float QS = 0.125f * 1.4426950408889634f;  // 1/sqrt(D) * log2(e)
    float2 c = *(const float2*)(cosd + n * D_ + d0);
    float2 s = *(const float2*)(sind + n * D_ + d0);
    const float qo0 = (qa * c.x - qb * s.x) * QS;
    const float qo1 = (qb * c.y + qa * s.y) * QS;
    const float ko0 = ka * c.x - kb * s.x;
    const float ko1 = kb * c.y + ka * s.y;

    const int bh = b * H_ + w;
    const size_t qi = ((size_t)bh * N_ + n) * D_ + d0;

    __half qh0 = __float2half_rn(qo0), qh1 = __float2half_rn(qo1);
    *(__half2*)&g_qh[qi] = __halves2half2(qh0, qh1);
    *(__half2*)&g_qh[QKP + qi] =
        __floats2half2_rn(qo0 - __half2float(qh0), qo1 - __half2float(qh1));
    *(__half2*)&g_kh[qi] = __floats2half2_rn(ko0, ko1);
}

// =====================================================================
// V transpose: g_qkv v-part [b][n][h*64+d] -> g_vh [bh][d][n] fp16
// =====================================================================
__global__ void vtrans_kernel()
{
    __shared__ float t[64][65];
    const int bh = blockIdx.x;
    const int n0 = blockIdx.y * 64;
    const int b = bh >> 4, h = bh & 15;
    const int tid = threadIdx.x;

    for (int i = tid; i < 4096; i += 256) {
        const int r = i >> 6, c = i & 63;
        t[c][r] = g_qkv[((size_t)(b * N_ + n0 + r)) * (3 * C_) + 2 * C_ + h * 64 + c];
    }
    __syncthreads();
    for (int i = tid; i < 4096; i += 256) {
        const int d = i >> 6, n = i & 63;
        g_vh[((size_t)bh * D_ + d) * N_ + n0 + n] = __float2half_rn(t[d][n]);
    }
}

// =====================================================================
// Flash attention fp16 2-pass: S = (Qhi+Qlo)*K, O += (Phi+Plo)*V.
// smem: Qhi|Qlo [128][64] fp16 (32KB) + 3 stages of K|V (32KB each) = 128KB
// =====================================================================
#define FSTG 32768
#define FLASH_SMEM (32768 + 3 * FSTG)

__global__ __launch_bounds__(256, 1)
void flash_mma(__half* __restrict__ outs)
{
    extern __shared__ char smem[];
    const uint32_t sb = smem_u32(smem);
    const int bh  = blockIdx.y;
    const int q0  = blockIdx.x * 128;
    const int tid = threadIdx.x;
    const int lane = tid & 31;
    const int wid  = tid >> 5;

    const __half* qhp = g_qh + (size_t)bh * N_ * D_;
    const __half* khp = g_kh + (size_t)bh * N_ * D_;
    const __half* vhp = g_vh + (size_t)bh * D_ * N_;

    int lrow[4], lc[4];
    uint32_t lsoff[4];
#pragma unroll
    for (int j = 0; j < 4; j++) {
        int idx = tid + 256 * j;
        lrow[j] = idx >> 3;
        lc[j] = idx & 7;
        lsoff[j] = (uint32_t)(lrow[j] * 128 + ((lc[j] ^ (lrow[j] & 7)) << 4));
    }

    // Q resident: hi@0, lo@16384
#pragma unroll
    for (int j = 0; j < 4; j++) {
        const __half* gq = qhp + (size_t)(q0 + lrow[j]) * D_ + lc[j] * 8;
        cpa16(sb + lsoff[j], gq);
        cpa16(sb + 16384 + lsoff[j], gq + QKP);
    }

    auto load_stage = [&](int buf, int kt) {
        const uint32_t st = sb + 32768 + buf * FSTG;
        const int kc0 = kt * 128;
#pragma unroll
        for (int j = 0; j < 4; j++) {
            const __half* gk = khp + (size_t)(kc0 + lrow[j]) * D_ + lc[j] * 8;
            cpa16(st + lsoff[j], gk);                   // K
            const int blk = lrow[j] >> 6, d = lrow[j] & 63;
            const __half* gv = vhp + (size_t)d * N_ + kc0 + blk * 64 + lc[j] * 8;
            cpa16(st + 16384 + lsoff[j], gv);           // V
        }
        CP_COMMIT();
    };

    load_stage(0, 0);
    load_stage(1, 1);
    load_stage(2, 2);

    const int swz = lane & 7;
    const int cA = lane >> 4;
    const int cB = (lane >> 3) & 1;
    const uint32_t aoff = (uint32_t)((wid * 16 + (lane & 15)) * 128);
    uint32_t boff[8];
#pragma unroll
    for (int nt = 0; nt < 8; nt++)
        boff[nt] = (uint32_t)((nt * 16 + ((lane >> 4) << 3) + (lane & 7)) * 128);

    float oc[8][4];
    float m_r[2], l_r[2];
#pragma unroll
    for (int i = 0; i < 8; i++)
#pragma unroll
        for (int j = 0; j < 4; j++) oc[i][j] = 0.f;
    m_r[0] = m_r[1] = -1e30f;
    l_r[0] = l_r[1] = 0.f;

    const int KTN = N_ / 128;
#pragma unroll 1
    for (int kt = 0; kt < KTN; kt++) {
        if (kt + 2 < KTN)      { CP_WAIT(2); }
        else if (kt + 1 < KTN) { CP_WAIT(1); }
        else                   { CP_WAIT(0); }
        __syncthreads();
        const uint32_t st = sb + 32768 + (kt % 3) * FSTG;

        // ---- S = Q K^T (2-pass fp16), log2 units ----
        float sc[16][4];
#pragma unroll
        for (int i = 0; i < 16; i++)
#pragma unroll
            for (int j = 0; j < 4; j++) sc[i][j] = 0.f;

#pragma unroll
        for (int kk = 0; kk < 4; kk++) {
            const uint32_t swA = (uint32_t)(((kk * 2 + cA) ^ swz) << 4);
            const uint32_t swB = (uint32_t)(((kk * 2 + cB) ^ swz) << 4);
            uint32_t aq[4], aql[4];
            ldm4(sb + aoff + swA, aq);
            ldm4(sb + 16384 + aoff + swA, aql);
#pragma unroll
            for (int nt = 0; nt < 8; nt++) {
                uint32_t kh[4];
                ldm4(st + boff[nt] + swB, kh);
#pragma unroll
                for (int h = 0; h < 2; h++) {
                    const int ng = nt * 2 + h;
                    mma_f16(sc[ng], aq, &kh[h * 2]);
                    mma_f16(sc[ng], aql, &kh[h * 2]);
                }
            }
        }

        // ---- online softmax (exp2) ----
#pragma unroll
        for (int p = 0; p < 2; p++) {
            float mx = -1e30f;
#pragma unroll
            for (int ng = 0; ng < 16; ng++)
                mx = fmaxf(mx, fmaxf(sc[ng][2 * p], sc[ng][2 * p + 1]));
            mx = fmaxf(mx, __shfl_xor_sync(0xffffffffu, mx, 1));
            mx = fmaxf(mx, __shfl_xor_sync(0xffffffffu, mx, 2));
            const float mnew = fmaxf(m_r[p], mx);
            const float f = exp2f(m_r[p] - mnew);
            m_r[p] = mnew;
            float rs = 0.f;
#pragma unroll
            for (int ng = 0; ng < 16; ng++) {
                sc[ng][2 * p]     = exp2f(sc[ng][2 * p] - mnew);
                sc[ng][2 * p + 1] = exp2f(sc[ng][2 * p + 1] - mnew);
                rs += sc[ng][2 * p] + sc[ng][2 * p + 1];
            }
            rs += __shfl_xor_sync(0xffffffffu, rs, 1);
            rs += __shfl_xor_sync(0xffffffffu, rs, 2);
            l_r[p] = l_r[p] * f + rs;
#pragma unroll
            for (int dt = 0; dt < 8; dt++) {
                oc[dt][2 * p] *= f;
                oc[dt][2 * p + 1] *= f;
            }
        }

        // ---- O += P V (2-pass: (Phi+Plo) * V) ----
#pragma unroll
        for (int kk = 0; kk < 8; kk++) {
            uint32_t ph[4], pl[4];
#pragma unroll
            for (int u = 0; u < 2; u++) {
                const int ng = 2 * kk + u;
#pragma unroll
                for (int v = 0; v < 2; v++) {
                    const float p0 = sc[ng][2 * v];
                    const float p1 = sc[ng][2 * v + 1];
                    const __half h0 = __float2half_rn(p0);
                    const __half h1 = __float2half_rn(p1);
                    __half2 hh = __halves2half2(h0, h1);
                    ph[u * 2 + v] = *(uint32_t*)&hh;
                    pl[u * 2 + v] = pack_h2(p0 - __half2float(h0),
                                            p1 - __half2float(h1));
                }
            }
            const int blk = kk >> 2, kin = kk & 3;
            const uint32_t swV = (uint32_t)(((kin * 2 + cB) ^ swz) << 4);
#pragma unroll
            for (int nt = 0; nt < 4; nt++) {
                const uint32_t voff = (uint32_t)((blk * 64 + nt * 16 +
                                     ((lane >> 4) << 3) + (lane & 7)) * 128);
                uint32_t vh[4];
                ldm4(st + 16384 + voff + swV, vh);
#pragma unroll
                for (int h2 = 0; h2 < 2; h2++) {
                    const int dt = nt * 2 + h2;
                    mma_f16(oc[dt], ph, &vh[h2 * 2]);
                    mma_f16(oc[dt], pl, &vh[h2 * 2]);
                }
            }
        }

        __syncthreads();
        if (kt + 3 < KTN) load_stage(kt % 3, kt + 3);
    }

    // ---- epilogue: O/l -> fp16 hi/lo planes in (B,N,C) layout ----
    const size_t nx = (size_t)BN_ * C_;
    const int b = bh >> 4, h = bh & 15;
#pragma unroll
    for (int p = 0; p < 2; p++) {
        const int n = q0 + wid * 16 + (lane >> 2) + 8 * p;
        const float inv = 1.f / l_r[p];
#pragma unroll
        for (int dt = 0; dt < 8; dt++) {
            const int d = dt * 8 + 2 * (lane & 3);
            const float v0 = oc[dt][2 * p] * inv;
            const float v1 = oc[dt][2 * p + 1] * inv;
            const __half h0 = __float2half_rn(v0);
            const __half h1 = __float2half_rn(v1);
            const size_t oi = ((size_t)(b * N_ + n)) * C_ + h * D_ + d;
            *(__half2*)&outs[oi] = __halves2half2(h0, h1);
            *(__half2*)&outs[nx + oi] =
                __floats2half2_rn(v0 - __half2float(h0), v1 - __half2float(h1));
        }
    }
}

// =====================================================================
extern "C" void kernel_launch(void* const* d_in, const int* in_sizes, int n_in,
                              void* d_out, int out_size)
{
    const float* x      = (const float*)d_in[0];
    const float* cosd   = (const float*)d_in[1];
    const float* sind   = (const float*)d_in[2];
    const float* w_qkv  = (const float*)d_in[3];
    const float* w_proj = (const float*)d_in[4];
    const float* q_gam  = (const float*)d_in[5];
    const float* k_gam  = (const float*)d_in[6];
    float* out = (float*)d_out;

    float* p_qkv = nullptr;
    __nv_bfloat16 *p_xs = nullptr, *p_wqkvs = nullptr;
    __half *p_atth = nullptr, *p_wprojh = nullptr;
    cudaGetSymbolAddress((void**)&p_qkv, g_qkv);
    cudaGetSymbolAddress((void**)&p_xs, g_xs);
    cudaGetSymbolAddress((void**)&p_wqkvs, g_wqkvs);
    cudaGetSymbolAddress((void**)&p_atth, g_atth);
    cudaGetSymbolAddress((void**)&p_wprojh, g_wprojh);

    const size_t n_x = (size_t)BN_ * C_;
    const size_t n_wqkv = (size_t)3 * C_ * C_;
    const size_t n_wproj = (size_t)C_ * C_;

    cudaFuncSetAttribute(gemm_mma,
                         cudaFuncAttributeMaxDynamicSharedMemorySize, GSMEM);
    cudaFuncSetAttribute(gemm2_mma,
                         cudaFuncAttributeMaxDynamicSharedMemorySize, GSMEM2);
    cudaFuncSetAttribute(flash_mma,
                         cudaFuncAttributeMaxDynamicSharedMemorySize, FLASH_SMEM);

    // 1) splits: x, w_qkv -> bf16 hi/lo; w_proj -> fp16
    split_kernel<<<(int)(n_x / 4 / 256), 256>>>(x, p_xs, n_x);
    split_kernel<<<(int)(n_wqkv / 4 / 256), 256>>>(w_qkv, p_wqkvs, n_wqkv);
    splith_kernel<<<(int)(n_wproj / 4 / 256), 256>>>(w_proj, p_wprojh, n_wproj);

    // 2) QKV projection (bf16x3 tensor cores)
    gemm_mma<<<dim3(3 * C_ / 128, BN_ / 128), 256, GSMEM>>>(
        p_xs, n_x, p_wqkvs, n_wqkv, p_qkv, 3 * C_, C_);

    // 3) RMSNorm + RoPE -> fp16; V transpose -> fp16
    prep_kernel<<<BN_, 512>>>(cosd, sind, q_gam, k_gam);
    vtrans_kernel<<<dim3(BH_, N_ / 64), 256>>>();

    // 4) flash attention (fp16 2-pass tensor cores)
    flash_mma<<<dim3(N_ / 128, BH_), 256, FLASH_SMEM>>>(p_atth);

    // 5) output projection (fp16 2-pass tensor cores)
    gemm2_mma<<<dim3(C_ / 128, BN_ / 128), 256, GSMEM2>>>(
        p_atth, n_x, p_wprojh, out, C_, C_);
}

// round 8
// speedup vs baseline: 2.6695x; 1.2580x over previous
#include <cuda_runtime.h>
#include <cuda_bf16.h>
#include <cuda_fp16.h>
#include <cstdint>
#include <math.h>

#define B_  4
#define N_  2048
#define C_  1024
#define H_  16
#define D_  64
#define BH_ (B_ * H_)   // 64
#define BN_ (B_ * N_)   // 8192

// ---------------- scratch (device globals; no allocations allowed) ----------
__device__ float g_qkv[(size_t)BN_ * 3 * C_];            // [b*n][3C]
__device__ __half g_xh[(size_t)2 * BN_ * C_];            // x: fp16 hi/lo
__device__ __half g_wqkvh[(size_t)3 * C_ * C_];          // w_qkv: fp16 (rounded)
__device__ __half g_wprojh[(size_t)C_ * C_];             // w_proj: fp16 (rounded)
__device__ __half g_atth[(size_t)2 * BN_ * C_];          // att: fp16 hi/lo
__device__ __half g_qh[(size_t)2 * BH_ * N_ * D_];       // q: fp16 hi/lo, pre-scaled
__device__ __half g_kh[(size_t)BH_ * N_ * D_];           // k: fp16 (rounded)
__device__ __half g_vh[(size_t)BH_ * D_ * N_];           // v: fp16 (rounded), [bh][d][n]

#define QKP ((size_t)BH_ * N_ * D_)   // plane stride for q hi/lo

// =====================================================================
// helpers (family-portable PTX only: cp.async / ldmatrix / mma.sync)
// =====================================================================
__device__ __forceinline__ uint32_t smem_u32(const void* p) {
    uint32_t a;
    asm("{ .reg .u64 t; cvta.to.shared.u64 t, %1; cvt.u32.u64 %0, t; }"
        : "=r"(a) : "l"(p));
    return a;
}

__device__ __forceinline__ void cpa16(uint32_t s, const void* g) {
    asm volatile("cp.async.cg.shared.global [%0], [%1], 16;"
                 :: "r"(s), "l"(g) : "memory");
}
#define CP_COMMIT()  asm volatile("cp.async.commit_group;" ::: "memory")
#define CP_WAIT(n)   asm volatile("cp.async.wait_group %0;" :: "n"(n) : "memory")

__device__ __forceinline__ void ldm4(uint32_t addr, uint32_t* r) {
    asm volatile("ldmatrix.sync.aligned.m8n8.x4.shared.b16 {%0,%1,%2,%3}, [%4];"
                 : "=r"(r[0]), "=r"(r[1]), "=r"(r[2]), "=r"(r[3]) : "r"(addr));
}

__device__ __forceinline__ void mma_f16(float* c, const uint32_t* a, const uint32_t* b) {
    asm volatile(
        "mma.sync.aligned.m16n8k16.row.col.f32.f16.f16.f32 "
        "{%0,%1,%2,%3}, {%4,%5,%6,%7}, {%8,%9}, {%0,%1,%2,%3};"
        : "+f"(c[0]), "+f"(c[1]), "+f"(c[2]), "+f"(c[3])
        : "r"(a[0]), "r"(a[1]), "r"(a[2]), "r"(a[3]), "r"(b[0]), "r"(b[1]));
}

// =====================================================================
// fp32 -> fp16 hi/lo split planes
// =====================================================================
__global__ void splith2_kernel(const float* __restrict__ src,
                               __half* __restrict__ dst, size_t n)
{
    size_t i = ((size_t)blockIdx.x * blockDim.x + threadIdx.x) * 4;
    if (i >= n) return;
    float4 v = *(const float4*)(src + i);
    __half h0 = __float2half_rn(v.x);
    __half h1 = __float2half_rn(v.y);
    __half h2 = __float2half_rn(v.z);
    __half h3 = __float2half_rn(v.w);
    __half2* hp = (__half2*)(dst + i);
    hp[0] = __halves2half2(h0, h1);
    hp[1] = __halves2half2(h2, h3);
    __half2* lp = (__half2*)(dst + n + i);
    lp[0] = __floats2half2_rn(v.x - __half2float(h0), v.y - __half2float(h1));
    lp[1] = __floats2half2_rn(v.z - __half2float(h2), v.w - __half2float(h3));
}

// fp32 -> fp16 (single rounded plane)
__global__ void splith_kernel(const float* __restrict__ src,
                              __half* __restrict__ dst, size_t n)
{
    size_t i = ((size_t)blockIdx.x * blockDim.x + threadIdx.x) * 4;
    if (i >= n) return;
    float4 v = *(const float4*)(src + i);
    __half2* hp = (__half2*)(dst + i);
    hp[0] = __floats2half2_rn(v.x, v.y);
    hp[1] = __floats2half2_rn(v.z, v.w);
}

// =====================================================================
// fp16 2-pass GEMM: C = (Ahi+Alo)[M,K] * B[N,K]^T, B pre-rounded fp16.
// stage: Ahi 16K | Alo 16K | B 16K = 48KB; 3 stages = 144KB.
// Used for both QKV and proj.
// =====================================================================
#define STG2 49152
#define GSMEM2 (3 * STG2)
__global__ __launch_bounds__(256, 1)
void gemm2_mma(const __half* __restrict__ A, size_t planeA,
               const __half* __restrict__ Bm,
               float* __restrict__ C, int ldC, int K)
{
    extern __shared__ char smem[];
    const uint32_t sb = smem_u32(smem);
    const int tid  = threadIdx.x;
    const int lane = tid & 31;
    const int wid  = tid >> 5;
    const int m0 = blockIdx.y * 128;
    const int n0 = blockIdx.x * 128;
    const int wm = (wid >> 2) * 64;
    const int wn = (wid & 3) * 32;

    int lrow[4], lc[4];
    uint32_t lsoff[4];
#pragma unroll
    for (int j = 0; j < 4; j++) {
        int idx = tid + 256 * j;
        lrow[j] = idx >> 3;
        lc[j] = idx & 7;
        lsoff[j] = (uint32_t)(lrow[j] * 128 + ((lc[j] ^ (lrow[j] & 7)) << 4));
    }

    uint32_t arow[4], brow[2];
#pragma unroll
    for (int mt = 0; mt < 4; mt++) arow[mt] = (uint32_t)((wm + mt * 16 + (lane & 15)) * 128);
#pragma unroll
    for (int nt = 0; nt < 2; nt++)
        brow[nt] = (uint32_t)((wn + nt * 16 + ((lane >> 4) << 3) + (lane & 7)) * 128);
    const int swz = lane & 7;
    const int cA = lane >> 4;
    const int cB = (lane >> 3) & 1;

    float acc[4][4][4];
#pragma unroll
    for (int i = 0; i < 4; i++)
#pragma unroll
        for (int j = 0; j < 4; j++)
#pragma unroll
            for (int r = 0; r < 4; r++) acc[i][j][r] = 0.f;

    const int KT = K >> 6;

    auto load_stage = [&](int buf, int kt) {
        const uint32_t st = sb + buf * STG2;
        const int k0 = kt * 64;
#pragma unroll
        for (int j = 0; j < 4; j++) {
            const __half* ga = A + (size_t)(m0 + lrow[j]) * K + k0 + lc[j] * 8;
            cpa16(st + lsoff[j], ga);
            cpa16(st + 16384 + lsoff[j], ga + planeA);
            const __half* gb = Bm + (size_t)(n0 + lrow[j]) * K + k0 + lc[j] * 8;
            cpa16(st + 32768 + lsoff[j], gb);
        }
        CP_COMMIT();
    };

    load_stage(0, 0);
    load_stage(1, 1);
    load_stage(2, 2);

#pragma unroll 1
    for (int kt = 0; kt < KT; kt++) {
        if (kt + 2 < KT)      { CP_WAIT(2); }
        else if (kt + 1 < KT) { CP_WAIT(1); }
        else                  { CP_WAIT(0); }
        __syncthreads();

        const uint32_t st = sb + (kt % 3) * STG2;
#pragma unroll
        for (int kk = 0; kk < 4; kk++) {
            uint32_t ah[4][4], al[4][4], bh[2][4];
            const uint32_t swA = (uint32_t)(((kk * 2 + cA) ^ swz) << 4);
            const uint32_t swB = (uint32_t)(((kk * 2 + cB) ^ swz) << 4);
#pragma unroll
            for (int mt = 0; mt < 4; mt++) {
                ldm4(st + arow[mt] + swA, ah[mt]);
                ldm4(st + 16384 + arow[mt] + swA, al[mt]);
            }
#pragma unroll
            for (int nt = 0; nt < 2; nt++)
                ldm4(st + 32768 + brow[nt] + swB, bh[nt]);
#pragma unroll
            for (int mt = 0; mt < 4; mt++)
#pragma unroll
                for (int nt = 0; nt < 2; nt++)
#pragma unroll
                    for (int h = 0; h < 2; h++) {
                        const int ng = nt * 2 + h;
                        mma_f16(acc[mt][ng], ah[mt], &bh[nt][h * 2]);
                        mma_f16(acc[mt][ng], al[mt], &bh[nt][h * 2]);
                    }
        }
        __syncthreads();
        if (kt + 3 < KT) load_stage(kt % 3, kt + 3);
    }

    const int g = lane >> 2, tg = lane & 3;
#pragma unroll
    for (int mt = 0; mt < 4; mt++)
#pragma unroll
        for (int ng = 0; ng < 4; ng++) {
            const int row = m0 + wm + mt * 16 + g;
            const int col = n0 + wn + ng * 8 + tg * 2;
            *(float2*)&C[(size_t)row * ldC + col] =
                make_float2(acc[mt][ng][0], acc[mt][ng][1]);
            *(float2*)&C[(size_t)(row + 8) * ldC + col] =
                make_float2(acc[mt][ng][2], acc[mt][ng][3]);
        }
}

// =====================================================================
// Prep: RMSNorm + RoPE -> q fp16 hi/lo (pre-scaled by log2e/sqrt(D)),
// k fp16 single. [bh][n][d] layout.
// =====================================================================
__global__ void prep_kernel(const float* __restrict__ cosd,
                            const float* __restrict__ sind,
                            const float* __restrict__ qg,
                            const float* __restrict__ kg)
{
    const int bn = blockIdx.x;
    const int n  = bn & (N_ - 1);
    const int b  = bn >> 11;
    const int w  = threadIdx.x >> 5;
    const int l  = threadIdx.x & 31;
    const int d0 = l * 2;

    const float* base = g_qkv + (size_t)bn * (3 * C_) + w * D_ + d0;
    float2 q = *(const float2*)(base);
    float2 k = *(const float2*)(base + C_);

    float sq = q.x * q.x + q.y * q.y;
    float sk = k.x * k.x + k.y * k.y;
#pragma unroll
    for (int ofs = 16; ofs >= 1; ofs >>= 1) {
        sq += __shfl_xor_sync(0xffffffffu, sq, ofs);
        sk += __shfl_xor_sync(0xffffffffu, sk, ofs);
    }
    const float rq = rsqrtf(sq * (1.f / 64.f) + 1e-6f);
    const float rk = rsqrtf(sk * (1.f / 64.f) + 1e-6f);

    float2 gq = *(const float2*)(qg + d0);
    float2 gk = *(const float2*)(kg + d0);
    const float qa = q.x * rq * gq.x, qb = q.y * rq * gq.y;
    const float ka = k.x * rk * gk.x, kb = k.y * rk * gk.y;

    const float QS = 0.125f * 1.4426950408889634f;  // 1/sqrt(D) * log2(e)
    float2 c = *(const float2*)(cosd + n * D_ + d0);
    float2 s = *(const float2*)(sind + n * D_ + d0);
    const float qo0 = (qa * c.x - qb * s.x) * QS;
    const float qo1 = (qb * c.y + qa * s.y) * QS;
    const float ko0 = ka * c.x - kb * s.x;
    const float ko1 = kb * c.y + ka * s.y;

    const int bh = b * H_ + w;
    const size_t qi = ((size_t)bh * N_ + n) * D_ + d0;

    __half qh0 = __float2half_rn(qo0), qh1 = __float2half_rn(qo1);
    *(__half2*)&g_qh[qi] = __halves2half2(qh0, qh1);
    *(__half2*)&g_qh[QKP + qi] =
        __floats2half2_rn(qo0 - __half2float(qh0), qo1 - __half2float(qh1));
    *(__half2*)&g_kh[qi] = __floats2half2_rn(ko0, ko1);
}

// =====================================================================
// V transpose: g_qkv v-part [b][n][h*64+d] -> g_vh [bh][d][n] fp16
// =====================================================================
__global__ void vtrans_kernel()
{
    __shared__ float t[64][65];
    const int bh = blockIdx.x;
    const int n0 = blockIdx.y * 64;
    const int b = bh >> 4, h = bh & 15;
    const int tid = threadIdx.x;

    for (int i = tid; i < 4096; i += 256) {
        const int r = i >> 6, c = i & 63;
        t[c][r] = g_qkv[((size_t)(b * N_ + n0 + r)) * (3 * C_) + 2 * C_ + h * 64 + c];
    }
    __syncthreads();
    for (int i = tid; i < 4096; i += 256) {
        const int d = i >> 6, n = i & 63;
        g_vh[((size_t)bh * D_ + d) * N_ + n0 + n] = __float2half_rn(t[d][n]);
    }
}

// =====================================================================
// Flash attention: S = (Qhi+Qlo)*K (2-pass), O += Phi*V (1-pass).
// smem: Qhi|Qlo [128][64] fp16 (32KB) + 3 stages of K|V (32KB each) = 128KB
// =====================================================================
#define FSTG 32768
#define FLASH_SMEM (32768 + 3 * FSTG)

__global__ __launch_bounds__(256, 1)
void flash_mma(__half* __restrict__ outs)
{
    extern __shared__ char smem[];
    const uint32_t sb = smem_u32(smem);
    const int bh  = blockIdx.y;
    const int q0  = blockIdx.x * 128;
    const int tid = threadIdx.x;
    const int lane = tid & 31;
    const int wid  = tid >> 5;

    const __half* qhp = g_qh + (size_t)bh * N_ * D_;
    const __half* khp = g_kh + (size_t)bh * N_ * D_;
    const __half* vhp = g_vh + (size_t)bh * D_ * N_;

    int lrow[4], lc[4];
    uint32_t lsoff[4];
#pragma unroll
    for (int j = 0; j < 4; j++) {
        int idx = tid + 256 * j;
        lrow[j] = idx >> 3;
        lc[j] = idx & 7;
        lsoff[j] = (uint32_t)(lrow[j] * 128 + ((lc[j] ^ (lrow[j] & 7)) << 4));
    }

    // Q resident: hi@0, lo@16384
#pragma unroll
    for (int j = 0; j < 4; j++) {
        const __half* gq = qhp + (size_t)(q0 + lrow[j]) * D_ + lc[j] * 8;
        cpa16(sb + lsoff[j], gq);
        cpa16(sb + 16384 + lsoff[j], gq + QKP);
    }

    auto load_stage = [&](int buf, int kt) {
        const uint32_t st = sb + 32768 + buf * FSTG;
        const int kc0 = kt * 128;
#pragma unroll
        for (int j = 0; j < 4; j++) {
            const __half* gk = khp + (size_t)(kc0 + lrow[j]) * D_ + lc[j] * 8;
            cpa16(st + lsoff[j], gk);                   // K
            const int blk = lrow[j] >> 6, d = lrow[j] & 63;
            const __half* gv = vhp + (size_t)d * N_ + kc0 + blk * 64 + lc[j] * 8;
            cpa16(st + 16384 + lsoff[j], gv);           // V
        }
        CP_COMMIT();
    };

    load_stage(0, 0);
    load_stage(1, 1);
    load_stage(2, 2);

    const int swz = lane & 7;
    const int cA = lane >> 4;
    const int cB = (lane >> 3) & 1;
    const uint32_t aoff = (uint32_t)((wid * 16 + (lane & 15)) * 128);
    uint32_t boff[8];
#pragma unroll
    for (int nt = 0; nt < 8; nt++)
        boff[nt] = (uint32_t)((nt * 16 + ((lane >> 4) << 3) + (lane & 7)) * 128);

    float oc[8][4];
    float m_r[2], l_r[2];
#pragma unroll
    for (int i = 0; i < 8; i++)
#pragma unroll
        for (int j = 0; j < 4; j++) oc[i][j] = 0.f;
    m_r[0] = m_r[1] = -1e30f;
    l_r[0] = l_r[1] = 0.f;

    const int KTN = N_ / 128;
#pragma unroll 1
    for (int kt = 0; kt < KTN; kt++) {
        if (kt + 2 < KTN)      { CP_WAIT(2); }
        else if (kt + 1 < KTN) { CP_WAIT(1); }
        else                   { CP_WAIT(0); }
        __syncthreads();
        const uint32_t st = sb + 32768 + (kt % 3) * FSTG;

        // ---- S = Q K^T (2-pass fp16), log2 units ----
        float sc[16][4];
#pragma unroll
        for (int i = 0; i < 16; i++)
#pragma unroll
            for (int j = 0; j < 4; j++) sc[i][j] = 0.f;

#pragma unroll
        for (int kk = 0; kk < 4; kk++) {
            const uint32_t swA = (uint32_t)(((kk * 2 + cA) ^ swz) << 4);
            const uint32_t swB = (uint32_t)(((kk * 2 + cB) ^ swz) << 4);
            uint32_t aq[4], aql[4];
            ldm4(sb + aoff + swA, aq);
            ldm4(sb + 16384 + aoff + swA, aql);
#pragma unroll
            for (int nt = 0; nt < 8; nt++) {
                uint32_t kh[4];
                ldm4(st + boff[nt] + swB, kh);
#pragma unroll
                for (int h = 0; h < 2; h++) {
                    const int ng = nt * 2 + h;
                    mma_f16(sc[ng], aq, &kh[h * 2]);
                    mma_f16(sc[ng], aql, &kh[h * 2]);
                }
            }
        }

        // ---- online softmax (exp2) ----
#pragma unroll
        for (int p = 0; p < 2; p++) {
            float mx = -1e30f;
#pragma unroll
            for (int ng = 0; ng < 16; ng++)
                mx = fmaxf(mx, fmaxf(sc[ng][2 * p], sc[ng][2 * p + 1]));
            mx = fmaxf(mx, __shfl_xor_sync(0xffffffffu, mx, 1));
            mx = fmaxf(mx, __shfl_xor_sync(0xffffffffu, mx, 2));
            const float mnew = fmaxf(m_r[p], mx);
            const float f = exp2f(m_r[p] - mnew);
            m_r[p] = mnew;
            float rs = 0.f;
#pragma unroll
            for (int ng = 0; ng < 16; ng++) {
                sc[ng][2 * p]     = exp2f(sc[ng][2 * p] - mnew);
                sc[ng][2 * p + 1] = exp2f(sc[ng][2 * p + 1] - mnew);
                rs += sc[ng][2 * p] + sc[ng][2 * p + 1];
            }
            rs += __shfl_xor_sync(0xffffffffu, rs, 1);
            rs += __shfl_xor_sync(0xffffffffu, rs, 2);
            l_r[p] = l_r[p] * f + rs;
#pragma unroll
            for (int dt = 0; dt < 8; dt++) {
                oc[dt][2 * p] *= f;
                oc[dt][2 * p + 1] *= f;
            }
        }

        // ---- O += P V (1-pass: P rounded fp16) ----
#pragma unroll
        for (int kk = 0; kk < 8; kk++) {
            uint32_t ph[4];
#pragma unroll
            for (int u = 0; u < 2; u++) {
                const int ng = 2 * kk + u;
#pragma unroll
                for (int v = 0; v < 2; v++) {
                    __half2 hh = __floats2half2_rn(sc[ng][2 * v], sc[ng][2 * v + 1]);
                    ph[u * 2 + v] = *(uint32_t*)&hh;
                }
            }
            const int blk = kk >> 2, kin = kk & 3;
            const uint32_t swV = (uint32_t)(((kin * 2 + cB) ^ swz) << 4);
#pragma unroll
            for (int nt = 0; nt < 4; nt++) {
                const uint32_t voff = (uint32_t)((blk * 64 + nt * 16 +
                                     ((lane >> 4) << 3) + (lane & 7)) * 128);
                uint32_t vh[4];
                ldm4(st + 16384 + voff + swV, vh);
#pragma unroll
                for (int h2 = 0; h2 < 2; h2++) {
                    const int dt = nt * 2 + h2;
                    mma_f16(oc[dt], ph, &vh[h2 * 2]);
                }
            }
        }

        __syncthreads();
        if (kt + 3 < KTN) load_stage(kt % 3, kt + 3);
    }

    // ---- epilogue: O/l -> fp16 hi/lo planes in (B,N,C) layout ----
    const size_t nx = (size_t)BN_ * C_;
    const int b = bh >> 4, h = bh & 15;
#pragma unroll
    for (int p = 0; p < 2; p++) {
        const int n = q0 + wid * 16 + (lane >> 2) + 8 * p;
        const float inv = 1.f / l_r[p];
#pragma unroll
        for (int dt = 0; dt < 8; dt++) {
            const int d = dt * 8 + 2 * (lane & 3);
            const float v0 = oc[dt][2 * p] * inv;
            const float v1 = oc[dt][2 * p + 1] * inv;
            const __half h0 = __float2half_rn(v0);
            const __half h1 = __float2half_rn(v1);
            const size_t oi = ((size_t)(b * N_ + n)) * C_ + h * D_ + d;
            *(__half2*)&outs[oi] = __halves2half2(h0, h1);
            *(__half2*)&outs[nx + oi] =
                __floats2half2_rn(v0 - __half2float(h0), v1 - __half2float(h1));
        }
    }
}

// =====================================================================
extern "C" void kernel_launch(void* const* d_in, const int* in_sizes, int n_in,
                              void* d_out, int out_size)
{
    const float* x      = (const float*)d_in[0];
    const float* cosd   = (const float*)d_in[1];
    const float* sind   = (const float*)d_in[2];
    const float* w_qkv  = (const float*)d_in[3];
    const float* w_proj = (const float*)d_in[4];
    const float* q_gam  = (const float*)d_in[5];
    const float* k_gam  = (const float*)d_in[6];
    float* out = (float*)d_out;

    float* p_qkv = nullptr;
    __half *p_xh = nullptr, *p_wqkvh = nullptr, *p_atth = nullptr, *p_wprojh = nullptr;
    cudaGetSymbolAddress((void**)&p_qkv, g_qkv);
    cudaGetSymbolAddress((void**)&p_xh, g_xh);
    cudaGetSymbolAddress((void**)&p_wqkvh, g_wqkvh);
    cudaGetSymbolAddress((void**)&p_atth, g_atth);
    cudaGetSymbolAddress((void**)&p_wprojh, g_wprojh);

    const size_t n_x = (size_t)BN_ * C_;
    const size_t n_wqkv = (size_t)3 * C_ * C_;
    const size_t n_wproj = (size_t)C_ * C_;

    cudaFuncSetAttribute(gemm2_mma,
                         cudaFuncAttributeMaxDynamicSharedMemorySize, GSMEM2);
    cudaFuncSetAttribute(flash_mma,
                         cudaFuncAttributeMaxDynamicSharedMemorySize, FLASH_SMEM);

    // 1) splits: x -> fp16 hi/lo; w_qkv, w_proj -> fp16
    splith2_kernel<<<(int)(n_x / 4 / 256), 256>>>(x, p_xh, n_x);
    splith_kernel<<<(int)(n_wqkv / 4 / 256), 256>>>(w_qkv, p_wqkvh, n_wqkv);
    splith_kernel<<<(int)(n_wproj / 4 / 256), 256>>>(w_proj, p_wprojh, n_wproj);

    // 2) QKV projection (fp16 2-pass tensor cores)
    gemm2_mma<<<dim3(3 * C_ / 128, BN_ / 128), 256, GSMEM2>>>(
        p_xh, n_x, p_wqkvh, p_qkv, 3 * C_, C_);

    // 3) RMSNorm + RoPE -> fp16; V transpose -> fp16
    prep_kernel<<<BN_, 512>>>(cosd, sind, q_gam, k_gam);
    vtrans_kernel<<<dim3(BH_, N_ / 64), 256>>>();

    // 4) flash attention (fp16: S 2-pass, PV 1-pass)
    flash_mma<<<dim3(N_ / 128, BH_), 256, FLASH_SMEM>>>(p_atth);

    // 5) output projection (fp16 2-pass tensor cores)
    gemm2_mma<<<dim3(C_ / 128, BN_ / 128), 256, GSMEM2>>>(
        p_atth, n_x, p_wprojh, out, C_, C_);
}

// round 9
// speedup vs baseline: 3.7069x; 1.3886x over previous
#include <cuda_runtime.h>
#include <cuda_bf16.h>
#include <cuda_fp16.h>
#include <cstdint>
#include <math.h>

#define B_  4
#define N_  2048
#define C_  1024
#define H_  16
#define D_  64
#define BH_ (B_ * H_)   // 64
#define BN_ (B_ * N_)   // 8192

// ---------------- scratch (device globals; no allocations allowed) ----------
__device__ float g_qkv[(size_t)BN_ * 3 * C_];            // [b*n][3C] fp32
__device__ __half g_xh[(size_t)BN_ * C_];                // x: fp16
__device__ __half g_wqkvh[(size_t)3 * C_ * C_];          // w_qkv: fp16
__device__ __half g_wprojh[(size_t)C_ * C_];             // w_proj: fp16
__device__ __half g_atth[(size_t)BN_ * C_];              // att: fp16
__device__ __half g_qh[(size_t)BH_ * N_ * D_];           // q: fp16, pre-scaled
__device__ __half g_kh[(size_t)BH_ * N_ * D_];           // k: fp16
__device__ __half g_vh[(size_t)BH_ * D_ * N_];           // v: fp16, [bh][d][n]

// =====================================================================
// helpers (family-portable PTX only: cp.async / ldmatrix / mma.sync)
// =====================================================================
__device__ __forceinline__ uint32_t smem_u32(const void* p) {
    uint32_t a;
    asm("{ .reg .u64 t; cvta.to.shared.u64 t, %1; cvt.u32.u64 %0, t; }"
        : "=r"(a) : "l"(p));
    return a;
}

__device__ __forceinline__ void cpa16(uint32_t s, const void* g) {
    asm volatile("cp.async.cg.shared.global [%0], [%1], 16;"
                 :: "r"(s), "l"(g) : "memory");
}
#define CP_COMMIT()  asm volatile("cp.async.commit_group;" ::: "memory")
#define CP_WAIT(n)   asm volatile("cp.async.wait_group %0;" :: "n"(n) : "memory")

__device__ __forceinline__ void ldm4(uint32_t addr, uint32_t* r) {
    asm volatile("ldmatrix.sync.aligned.m8n8.x4.shared.b16 {%0,%1,%2,%3}, [%4];"
                 : "=r"(r[0]), "=r"(r[1]), "=r"(r[2]), "=r"(r[3]) : "r"(addr));
}

__device__ __forceinline__ void mma_f16(float* c, const uint32_t* a, const uint32_t* b) {
    asm volatile(
        "mma.sync.aligned.m16n8k16.row.col.f32.f16.f16.f32 "
        "{%0,%1,%2,%3}, {%4,%5,%6,%7}, {%8,%9}, {%0,%1,%2,%3};"
        : "+f"(c[0]), "+f"(c[1]), "+f"(c[2]), "+f"(c[3])
        : "r"(a[0]), "r"(a[1]), "r"(a[2]), "r"(a[3]), "r"(b[0]), "r"(b[1]));
}

// fp32 -> fp16 (single rounded plane)
__global__ void splith_kernel(const float* __restrict__ src,
                              __half* __restrict__ dst, size_t n)
{
    size_t i = ((size_t)blockIdx.x * blockDim.x + threadIdx.x) * 4;
    if (i >= n) return;
    float4 v = *(const float4*)(src + i);
    __half2* hp = (__half2*)(dst + i);
    hp[0] = __floats2half2_rn(v.x, v.y);
    hp[1] = __floats2half2_rn(v.z, v.w);
}

// =====================================================================
// fp16 1-pass GEMM: C[M,N] = A[M,K] * B[N,K]^T (both fp16 rounded).
// stage: A 16K | B 16K = 32KB; 4 stages = 128KB. Single barrier/iter.
// =====================================================================
#define STG1 32768
#define GSMEM1 (4 * STG1)
__global__ __launch_bounds__(256, 1)
void gemm1_mma(const __half* __restrict__ A, const __half* __restrict__ Bm,
               float* __restrict__ C, int ldC, int K)
{
    extern __shared__ char smem[];
    const uint32_t sb = smem_u32(smem);
    const int tid  = threadIdx.x;
    const int lane = tid & 31;
    const int wid  = tid >> 5;
    const int m0 = blockIdx.y * 128;
    const int n0 = blockIdx.x * 128;
    const int wm = (wid >> 2) * 64;
    const int wn = (wid & 3) * 32;

    int lrow[4], lc[4];
    uint32_t lsoff[4];
#pragma unroll
    for (int j = 0; j < 4; j++) {
        int idx = tid + 256 * j;
        lrow[j] = idx >> 3;
        lc[j] = idx & 7;
        lsoff[j] = (uint32_t)(lrow[j] * 128 + ((lc[j] ^ (lrow[j] & 7)) << 4));
    }

    uint32_t arow[4], brow[2];
#pragma unroll
    for (int mt = 0; mt < 4; mt++) arow[mt] = (uint32_t)((wm + mt * 16 + (lane & 15)) * 128);
#pragma unroll
    for (int nt = 0; nt < 2; nt++)
        brow[nt] = (uint32_t)((wn + nt * 16 + ((lane >> 4) << 3) + (lane & 7)) * 128);
    const int swz = lane & 7;
    const int cA = lane >> 4;
    const int cB = (lane >> 3) & 1;

    float acc[4][4][4];
#pragma unroll
    for (int i = 0; i < 4; i++)
#pragma unroll
        for (int j = 0; j < 4; j++)
#pragma unroll
            for (int r = 0; r < 4; r++) acc[i][j][r] = 0.f;

    const int KT = K >> 6;

    auto load_stage = [&](int buf, int kt) {
        const uint32_t st = sb + buf * STG1;
        const int k0 = kt * 64;
#pragma unroll
        for (int j = 0; j < 4; j++) {
            cpa16(st + lsoff[j], A + (size_t)(m0 + lrow[j]) * K + k0 + lc[j] * 8);
            cpa16(st + 16384 + lsoff[j],
                  Bm + (size_t)(n0 + lrow[j]) * K + k0 + lc[j] * 8);
        }
        CP_COMMIT();
    };

    load_stage(0, 0);
    load_stage(1, 1);
    load_stage(2, 2);

#pragma unroll 1
    for (int kt = 0; kt < KT; kt++) {
        if (kt + 2 < KT)      { CP_WAIT(2); }
        else if (kt + 1 < KT) { CP_WAIT(1); }
        else                  { CP_WAIT(0); }
        __syncthreads();
        if (kt + 3 < KT) load_stage((kt + 3) & 3, kt + 3);  // buffer (kt-1)&3: drained

        const uint32_t st = sb + (kt & 3) * STG1;
#pragma unroll
        for (int kk = 0; kk < 4; kk++) {
            uint32_t ah[4][4], bh[2][4];
            const uint32_t swA = (uint32_t)(((kk * 2 + cA) ^ swz) << 4);
            const uint32_t swB = (uint32_t)(((kk * 2 + cB) ^ swz) << 4);
#pragma unroll
            for (int mt = 0; mt < 4; mt++) ldm4(st + arow[mt] + swA, ah[mt]);
#pragma unroll
            for (int nt = 0; nt < 2; nt++) ldm4(st + 16384 + brow[nt] + swB, bh[nt]);
#pragma unroll
            for (int mt = 0; mt < 4; mt++)
#pragma unroll
                for (int nt = 0; nt < 2; nt++)
#pragma unroll
                    for (int h = 0; h < 2; h++)
                        mma_f16(acc[mt][nt * 2 + h], ah[mt], &bh[nt][h * 2]);
        }
    }

    const int g = lane >> 2, tg = lane & 3;
#pragma unroll
    for (int mt = 0; mt < 4; mt++)
#pragma unroll
        for (int ng = 0; ng < 4; ng++) {
            const int row = m0 + wm + mt * 16 + g;
            const int col = n0 + wn + ng * 8 + tg * 2;
            *(float2*)&C[(size_t)row * ldC + col] =
                make_float2(acc[mt][ng][0], acc[mt][ng][1]);
            *(float2*)&C[(size_t)(row + 8) * ldC + col] =
                make_float2(acc[mt][ng][2], acc[mt][ng][3]);
        }
}

// =====================================================================
// Prep: RMSNorm + RoPE -> q fp16 (pre-scaled by log2e/sqrt(D)), k fp16.
// =====================================================================
__global__ void prep_kernel(const float* __restrict__ cosd,
                            const float* __restrict__ sind,
                            const float* __restrict__ qg,
                            const float* __restrict__ kg)
{
    const int bn = blockIdx.x;
    const int n  = bn & (N_ - 1);
    const int b  = bn >> 11;
    const int w  = threadIdx.x >> 5;
    const int l  = threadIdx.x & 31;
    const int d0 = l * 2;

    const float* base = g_qkv + (size_t)bn * (3 * C_) + w * D_ + d0;
    float2 q = *(const float2*)(base);
    float2 k = *(const float2*)(base + C_);

    float sq = q.x * q.x + q.y * q.y;
    float sk = k.x * k.x + k.y * k.y;
#pragma unroll
    for (int ofs = 16; ofs >= 1; ofs >>= 1) {
        sq += __shfl_xor_sync(0xffffffffu, sq, ofs);
        sk += __shfl_xor_sync(0xffffffffu, sk, ofs);
    }
    const float rq = rsqrtf(sq * (1.f / 64.f) + 1e-6f);
    const float rk = rsqrtf(sk * (1.f / 64.f) + 1e-6f);

    float2 gq = *(const float2*)(qg + d0);
    float2 gk = *(const float2*)(kg + d0);
    const float qa = q.x * rq * gq.x, qb = q.y * rq * gq.y;
    const float ka = k.x * rk * gk.x, kb = k.y * rk * gk.y;

    const float QS = 0.125f * 1.4426950408889634f;  // 1/sqrt(D) * log2(e)
    float2 c = *(const float2*)(cosd + n * D_ + d0);
    float2 s = *(const float2*)(sind + n * D_ + d0);
    const float qo0 = (qa * c.x - qb * s.x) * QS;
    const float qo1 = (qb * c.y + qa * s.y) * QS;
    const float ko0 = ka * c.x - kb * s.x;
    const float ko1 = kb * c.y + ka * s.y;

    const int bh = b * H_ + w;
    const size_t qi = ((size_t)bh * N_ + n) * D_ + d0;
    *(__half2*)&g_qh[qi] = __floats2half2_rn(qo0, qo1);
    *(__half2*)&g_kh[qi] = __floats2half2_rn(ko0, ko1);
}

// =====================================================================
// V transpose: g_qkv v-part [b][n][h*64+d] -> g_vh [bh][d][n] fp16
// =====================================================================
__global__ void vtrans_kernel()
{
    __shared__ float t[64][65];
    const int bh = blockIdx.x;
    const int n0 = blockIdx.y * 64;
    const int b = bh >> 4, h = bh & 15;
    const int tid = threadIdx.x;

    for (int i = tid; i < 4096; i += 256) {
        const int r = i >> 6, c = i & 63;
        t[c][r] = g_qkv[((size_t)(b * N_ + n0 + r)) * (3 * C_) + 2 * C_ + h * 64 + c];
    }
    __syncthreads();
    for (int i = tid; i < 4096; i += 256) {
        const int d = i >> 6, n = i & 63;
        g_vh[((size_t)bh * D_ + d) * N_ + n0 + n] = __float2half_rn(t[d][n]);
    }
}

// =====================================================================
// Flash attention fp16 (S 1-pass, PV 1-pass).
// smem: Q [128][64] fp16 (16KB) + 4 stages of K|V (32KB each) = 144KB.
// Single barrier per k-iteration.
// =====================================================================
#define FSTG 32768
#define FLASH_SMEM (16384 + 4 * FSTG)

__global__ __launch_bounds__(256, 1)
void flash_mma(__half* __restrict__ outs)
{
    extern __shared__ char smem[];
    const uint32_t sb = smem_u32(smem);
    const int bh  = blockIdx.y;
    const int q0  = blockIdx.x * 128;
    const int tid = threadIdx.x;
    const int lane = tid & 31;
    const int wid  = tid >> 5;

    const __half* qhp = g_qh + (size_t)bh * N_ * D_;
    const __half* khp = g_kh + (size_t)bh * N_ * D_;
    const __half* vhp = g_vh + (size_t)bh * D_ * N_;

    int lrow[4], lc[4];
    uint32_t lsoff[4];
#pragma unroll
    for (int j = 0; j < 4; j++) {
        int idx = tid + 256 * j;
        lrow[j] = idx >> 3;
        lc[j] = idx & 7;
        lsoff[j] = (uint32_t)(lrow[j] * 128 + ((lc[j] ^ (lrow[j] & 7)) << 4));
    }

    // Q resident (16KB), folded into group 0
#pragma unroll
    for (int j = 0; j < 4; j++)
        cpa16(sb + lsoff[j], qhp + (size_t)(q0 + lrow[j]) * D_ + lc[j] * 8);

    auto load_stage = [&](int buf, int kt) {
        const uint32_t st = sb + 16384 + buf * FSTG;
        const int kc0 = kt * 128;
#pragma unroll
        for (int j = 0; j < 4; j++) {
            cpa16(st + lsoff[j], khp + (size_t)(kc0 + lrow[j]) * D_ + lc[j] * 8);
            const int blk = lrow[j] >> 6, d = lrow[j] & 63;
            cpa16(st + 16384 + lsoff[j],
                  vhp + (size_t)d * N_ + kc0 + blk * 64 + lc[j] * 8);
        }
        CP_COMMIT();
    };

    load_stage(0, 0);
    load_stage(1, 1);
    load_stage(2, 2);

    const int swz = lane & 7;
    const int cA = lane >> 4;
    const int cB = (lane >> 3) & 1;
    const uint32_t aoff = (uint32_t)((wid * 16 + (lane & 15)) * 128);
    uint32_t boff[8];
#pragma unroll
    for (int nt = 0; nt < 8; nt++)
        boff[nt] = (uint32_t)((nt * 16 + ((lane >> 4) << 3) + (lane & 7)) * 128);

    float oc[8][4];
    float m_r[2], l_r[2];
#pragma unroll
    for (int i = 0; i < 8; i++)
#pragma unroll
        for (int j = 0; j < 4; j++) oc[i][j] = 0.f;
    m_r[0] = m_r[1] = -1e30f;
    l_r[0] = l_r[1] = 0.f;

    const int KTN = N_ / 128;
#pragma unroll 1
    for (int kt = 0; kt < KTN; kt++) {
        if (kt + 2 < KTN)      { CP_WAIT(2); }
        else if (kt + 1 < KTN) { CP_WAIT(1); }
        else                   { CP_WAIT(0); }
        __syncthreads();
        if (kt + 3 < KTN) load_stage((kt + 3) & 3, kt + 3);  // buffer (kt-1)&3: drained
        const uint32_t st = sb + 16384 + (kt & 3) * FSTG;

        // ---- S = Q K^T (1-pass fp16), log2 units ----
        float sc[16][4];
#pragma unroll
        for (int i = 0; i < 16; i++)
#pragma unroll
            for (int j = 0; j < 4; j++) sc[i][j] = 0.f;

#pragma unroll
        for (int kk = 0; kk < 4; kk++) {
            const uint32_t swA = (uint32_t)(((kk * 2 + cA) ^ swz) << 4);
            const uint32_t swB = (uint32_t)(((kk * 2 + cB) ^ swz) << 4);
            uint32_t aq[4];
            ldm4(sb + aoff + swA, aq);
#pragma unroll
            for (int nt = 0; nt < 8; nt++) {
                uint32_t kh[4];
                ldm4(st + boff[nt] + swB, kh);
#pragma unroll
                for (int h = 0; h < 2; h++)
                    mma_f16(sc[nt * 2 + h], aq, &kh[h * 2]);
            }
        }

        // ---- online softmax (exp2) ----
#pragma unroll
        for (int p = 0; p < 2; p++) {
            float mx = -1e30f;
#pragma unroll
            for (int ng = 0; ng < 16; ng++)
                mx = fmaxf(mx, fmaxf(sc[ng][2 * p], sc[ng][2 * p + 1]));
            mx = fmaxf(mx, __shfl_xor_sync(0xffffffffu, mx, 1));
            mx = fmaxf(mx, __shfl_xor_sync(0xffffffffu, mx, 2));
            const float mnew = fmaxf(m_r[p], mx);
            const float f = exp2f(m_r[p] - mnew);
            m_r[p] = mnew;
            float rs = 0.f;
#pragma unroll
            for (int ng = 0; ng < 16; ng++) {
                sc[ng][2 * p]     = exp2f(sc[ng][2 * p] - mnew);
                sc[ng][2 * p + 1] = exp2f(sc[ng][2 * p + 1] - mnew);
                rs += sc[ng][2 * p] + sc[ng][2 * p + 1];
            }
            rs += __shfl_xor_sync(0xffffffffu, rs, 1);
            rs += __shfl_xor_sync(0xffffffffu, rs, 2);
            l_r[p] = l_r[p] * f + rs;
#pragma unroll
            for (int dt = 0; dt < 8; dt++) {
                oc[dt][2 * p] *= f;
                oc[dt][2 * p + 1] *= f;
            }
        }

        // ---- O += P V (1-pass: P rounded fp16) ----
#pragma unroll
        for (int kk = 0; kk < 8; kk++) {
            uint32_t ph[4];
#pragma unroll
            for (int u = 0; u < 2; u++) {
                const int ng = 2 * kk + u;
#pragma unroll
                for (int v = 0; v < 2; v++) {
                    __half2 hh = __floats2half2_rn(sc[ng][2 * v], sc[ng][2 * v + 1]);
                    ph[u * 2 + v] = *(uint32_t*)&hh;
                }
            }
            const int blk = kk >> 2, kin = kk & 3;
            const uint32_t swV = (uint32_t)(((kin * 2 + cB) ^ swz) << 4);
#pragma unroll
            for (int nt = 0; nt < 4; nt++) {
                const uint32_t voff = (uint32_t)((blk * 64 + nt * 16 +
                                     ((lane >> 4) << 3) + (lane & 7)) * 128);
                uint32_t vh[4];
                ldm4(st + 16384 + voff + swV, vh);
#pragma unroll
                for (int h2 = 0; h2 < 2; h2++)
                    mma_f16(oc[nt * 2 + h2], ph, &vh[h2 * 2]);
            }
        }
    }

    // ---- epilogue: O/l -> fp16 in (B,N,C) layout ----
    const int b = bh >> 4, h = bh & 15;
#pragma unroll
    for (int p = 0; p < 2; p++) {
        const int n = q0 + wid * 16 + (lane >> 2) + 8 * p;
        const float inv = 1.f / l_r[p];
#pragma unroll
        for (int dt = 0; dt < 8; dt++) {
            const int d = dt * 8 + 2 * (lane & 3);
            const size_t oi = ((size_t)(b * N_ + n)) * C_ + h * D_ + d;
            *(__half2*)&outs[oi] =
                __floats2half2_rn(oc[dt][2 * p] * inv, oc[dt][2 * p + 1] * inv);
        }
    }
}

// =====================================================================
extern "C" void kernel_launch(void* const* d_in, const int* in_sizes, int n_in,
                              void* d_out, int out_size)
{
    const float* x      = (const float*)d_in[0];
    const float* cosd   = (const float*)d_in[1];
    const float* sind   = (const float*)d_in[2];
    const float* w_qkv  = (const float*)d_in[3];
    const float* w_proj = (const float*)d_in[4];
    const float* q_gam  = (const float*)d_in[5];
    const float* k_gam  = (const float*)d_in[6];
    float* out = (float*)d_out;

    float* p_qkv = nullptr;
    __half *p_xh = nullptr, *p_wqkvh = nullptr, *p_atth = nullptr, *p_wprojh = nullptr;
    cudaGetSymbolAddress((void**)&p_qkv, g_qkv);
    cudaGetSymbolAddress((void**)&p_xh, g_xh);
    cudaGetSymbolAddress((void**)&p_wqkvh, g_wqkvh);
    cudaGetSymbolAddress((void**)&p_atth, g_atth);
    cudaGetSymbolAddress((void**)&p_wprojh, g_wprojh);

    const size_t n_x = (size_t)BN_ * C_;
    const size_t n_wqkv = (size_t)3 * C_ * C_;
    const size_t n_wproj = (size_t)C_ * C_;

    cudaFuncSetAttribute(gemm1_mma,
                         cudaFuncAttributeMaxDynamicSharedMemorySize, GSMEM1);
    cudaFuncSetAttribute(flash_mma,
                         cudaFuncAttributeMaxDynamicSharedMemorySize, FLASH_SMEM);

    // 1) splits: x, w_qkv, w_proj -> fp16
    splith_kernel<<<(int)(n_x / 4 / 256), 256>>>(x, p_xh, n_x);
    splith_kernel<<<(int)(n_wqkv / 4 / 256), 256>>>(w_qkv, p_wqkvh, n_wqkv);
    splith_kernel<<<(int)(n_wproj / 4 / 256), 256>>>(w_proj, p_wprojh, n_wproj);

    // 2) QKV projection (fp16 tensor cores)
    gemm1_mma<<<dim3(3 * C_ / 128, BN_ / 128), 256, GSMEM1>>>(
        p_xh, p_wqkvh, p_qkv, 3 * C_, C_);

    // 3) RMSNorm + RoPE -> fp16; V transpose -> fp16
    prep_kernel<<<BN_, 512>>>(cosd, sind, q_gam, k_gam);
    vtrans_kernel<<<dim3(BH_, N_ / 64), 256>>>();

    // 4) flash attention (fp16 tensor cores)
    flash_mma<<<dim3(N_ / 128, BH_), 256, FLASH_SMEM>>>(p_atth);

    // 5) output projection (fp16 tensor cores)
    gemm1_mma<<<dim3(C_ / 128, BN_ / 128), 256, GSMEM1>>>(
        p_atth, p_wprojh, out, C_, C_);
}

// round 10
// speedup vs baseline: 3.7072x; 1.0001x over previous
#include <cuda_runtime.h>
#include <cuda_bf16.h>
#include <cuda_fp16.h>
#include <cstdint>
#include <math.h>

#define B_  4
#define N_  2048
#define C_  1024
#define H_  16
#define D_  64
#define BH_ (B_ * H_)   // 64
#define BN_ (B_ * N_)   // 8192

// ---------------- scratch (device globals; no allocations allowed) ----------
__device__ float g_qkv[(size_t)BN_ * 3 * C_];            // [b*n][3C] fp32
__device__ __half g_xh[(size_t)BN_ * C_];                // x: fp16
__device__ __half g_wqkvh[(size_t)3 * C_ * C_];          // w_qkv: fp16
__device__ __half g_wprojh[(size_t)C_ * C_];             // w_proj: fp16
__device__ __half g_atth[(size_t)BN_ * C_];              // att: fp16
__device__ __half g_qh[(size_t)BH_ * N_ * D_];           // q: fp16, pre-scaled
__device__ __half g_kh[(size_t)BH_ * N_ * D_];           // k: fp16
__device__ __half g_vh[(size_t)BH_ * D_ * N_];           // v: fp16, [bh][d][n]

// =====================================================================
// helpers
// =====================================================================
__device__ __forceinline__ uint32_t smem_u32(const void* p) {
    uint32_t a;
    asm("{ .reg .u64 t; cvta.to.shared.u64 t, %1; cvt.u32.u64 %0, t; }"
        : "=r"(a) : "l"(p));
    return a;
}

__device__ __forceinline__ void cpa16(uint32_t s, const void* g) {
    asm volatile("cp.async.cg.shared.global [%0], [%1], 16;"
                 :: "r"(s), "l"(g) : "memory");
}
#define CP_COMMIT()  asm volatile("cp.async.commit_group;" ::: "memory")
#define CP_WAIT(n)   asm volatile("cp.async.wait_group %0;" :: "n"(n) : "memory")

__device__ __forceinline__ void ldm4(uint32_t addr, uint32_t* r) {
    asm volatile("ldmatrix.sync.aligned.m8n8.x4.shared.b16 {%0,%1,%2,%3}, [%4];"
                 : "=r"(r[0]), "=r"(r[1]), "=r"(r[2]), "=r"(r[3]) : "r"(addr));
}

__device__ __forceinline__ void mma_f16(float* c, const uint32_t* a, const uint32_t* b) {
    asm volatile(
        "mma.sync.aligned.m16n8k16.row.col.f32.f16.f16.f32 "
        "{%0,%1,%2,%3}, {%4,%5,%6,%7}, {%8,%9}, {%0,%1,%2,%3};"
        : "+f"(c[0]), "+f"(c[1]), "+f"(c[2]), "+f"(c[3])
        : "r"(a[0]), "r"(a[1]), "r"(a[2]), "r"(a[3]), "r"(b[0]), "r"(b[1]));
}

// fp32 -> fp16 (single rounded plane)
__global__ void splith_kernel(const float* __restrict__ src,
                              __half* __restrict__ dst, size_t n)
{
    size_t i = ((size_t)blockIdx.x * blockDim.x + threadIdx.x) * 4;
    if (i >= n) return;
    float4 v = *(const float4*)(src + i);
    __half2* hp = (__half2*)(dst + i);
    hp[0] = __floats2half2_rn(v.x, v.y);
    hp[1] = __floats2half2_rn(v.z, v.w);
}

// =====================================================================
// fp16 GEMM: C[M,N] = A[M,K]*B[N,K]^T.  CTA 128x256, warp tile 64x64.
// stage: A[128][64] 16KB @0 | B[256][64] 32KB @16384 = 48KB; 4 stages.
// Single barrier per k-iteration.
// =====================================================================
#define STG1 49152
#define GSMEM1 (4 * STG1)
__global__ __launch_bounds__(256, 1)
void gemm1_mma(const __half* __restrict__ A, const __half* __restrict__ Bm,
               float* __restrict__ C, int ldC, int K)
{
    extern __shared__ char smem[];
    const uint32_t sb = smem_u32(smem);
    const int tid  = threadIdx.x;
    const int lane = tid & 31;
    const int wid  = tid >> 5;
    const int m0 = blockIdx.y * 128;
    const int n0 = blockIdx.x * 256;
    const int wm = (wid >> 2) * 64;
    const int wn = (wid & 3) * 64;

    // load descriptors: A 1024 chunks (4/thread), B 2048 chunks (8/thread)
    uint32_t sA[4]; const __half* pA[4];
#pragma unroll
    for (int j = 0; j < 4; j++) {
        const int idx = tid + 256 * j;
        const int r = idx >> 3, c = idx & 7;
        sA[j] = (uint32_t)(r * 128 + ((c ^ (r & 7)) << 4));
        pA[j] = A + (size_t)(m0 + r) * K + c * 8;
    }
    uint32_t sB[8]; const __half* pB[8];
#pragma unroll
    for (int j = 0; j < 8; j++) {
        const int idx = tid + 256 * j;
        const int r = idx >> 3, c = idx & 7;
        sB[j] = (uint32_t)(16384 + r * 128 + ((c ^ (r & 7)) << 4));
        pB[j] = Bm + (size_t)(n0 + r) * K + c * 8;
    }

    uint32_t arow[4], brow[4];
#pragma unroll
    for (int mt = 0; mt < 4; mt++)
        arow[mt] = (uint32_t)((wm + mt * 16 + (lane & 15)) * 128);
#pragma unroll
    for (int nt = 0; nt < 4; nt++)
        brow[nt] = (uint32_t)(16384 +
            (wn + nt * 16 + ((lane >> 4) << 3) + (lane & 7)) * 128);
    const int swz = lane & 7;
    const int cA = lane >> 4;
    const int cB = (lane >> 3) & 1;

    float acc[4][8][4];
#pragma unroll
    for (int i = 0; i < 4; i++)
#pragma unroll
        for (int j = 0; j < 8; j++)
#pragma unroll
            for (int r = 0; r < 4; r++) acc[i][j][r] = 0.f;

    const int KT = K >> 6;

    auto load_stage = [&](int buf, int kt) {
        const uint32_t st = sb + buf * STG1;
        const int k0 = kt * 64;
#pragma unroll
        for (int j = 0; j < 4; j++) cpa16(st + sA[j], pA[j] + k0);
#pragma unroll
        for (int j = 0; j < 8; j++) cpa16(st + sB[j], pB[j] + k0);
        CP_COMMIT();
    };

    load_stage(0, 0);
    load_stage(1, 1);
    load_stage(2, 2);

#pragma unroll 1
    for (int kt = 0; kt < KT; kt++) {
        if (kt + 2 < KT)      { CP_WAIT(2); }
        else if (kt + 1 < KT) { CP_WAIT(1); }
        else                  { CP_WAIT(0); }
        __syncthreads();
        if (kt + 3 < KT) load_stage((kt + 3) & 3, kt + 3);  // buf (kt-1)&3 drained

        const uint32_t st = sb + (kt & 3) * STG1;
#pragma unroll
        for (int kk = 0; kk < 4; kk++) {
            uint32_t ah[4][4], bh[4][4];
            const uint32_t swA = (uint32_t)(((kk * 2 + cA) ^ swz) << 4);
            const uint32_t swB = (uint32_t)(((kk * 2 + cB) ^ swz) << 4);
#pragma unroll
            for (int mt = 0; mt < 4; mt++) ldm4(st + arow[mt] + swA, ah[mt]);
#pragma unroll
            for (int nt = 0; nt < 4; nt++) ldm4(st + brow[nt] + swB, bh[nt]);
#pragma unroll
            for (int mt = 0; mt < 4; mt++)
#pragma unroll
                for (int nt = 0; nt < 4; nt++)
#pragma unroll
                    for (int h = 0; h < 2; h++)
                        mma_f16(acc[mt][nt * 2 + h], ah[mt], &bh[nt][h * 2]);
        }
    }

    const int g = lane >> 2, tg = lane & 3;
#pragma unroll
    for (int mt = 0; mt < 4; mt++)
#pragma unroll
        for (int ng = 0; ng < 8; ng++) {
            const int row = m0 + wm + mt * 16 + g;
            const int col = n0 + wn + ng * 8 + tg * 2;
            *(float2*)&C[(size_t)row * ldC + col] =
                make_float2(acc[mt][ng][0], acc[mt][ng][1]);
            *(float2*)&C[(size_t)(row + 8) * ldC + col] =
                make_float2(acc[mt][ng][2], acc[mt][ng][3]);
        }
}

// =====================================================================
// Prep: RMSNorm + RoPE -> q fp16 (pre-scaled by log2e/sqrt(D)), k fp16.
// =====================================================================
__global__ void prep_kernel(const float* __restrict__ cosd,
                            const float* __restrict__ sind,
                            const float* __restrict__ qg,
                            const float* __restrict__ kg)
{
    const int bn = blockIdx.x;
    const int n  = bn & (N_ - 1);
    const int b  = bn >> 11;
    const int w  = threadIdx.x >> 5;
    const int l  = threadIdx.x & 31;
    const int d0 = l * 2;

    const float* base = g_qkv + (size_t)bn * (3 * C_) + w * D_ + d0;
    float2 q = *(const float2*)(base);
    float2 k = *(const float2*)(base + C_);

    float sq = q.x * q.x + q.y * q.y;
    float sk = k.x * k.x + k.y * k.y;
#pragma unroll
    for (int ofs = 16; ofs >= 1; ofs >>= 1) {
        sq += __shfl_xor_sync(0xffffffffu, sq, ofs);
        sk += __shfl_xor_sync(0xffffffffu, sk, ofs);
    }
    const float rq = rsqrtf(sq * (1.f / 64.f) + 1e-6f);
    const float rk = rsqrtf(sk * (1.f / 64.f) + 1e-6f);

    float2 gq = *(const float2*)(qg + d0);
    float2 gk = *(const float2*)(kg + d0);
    const float qa = q.x * rq * gq.x, qb = q.y * rq * gq.y;
    const float ka = k.x * rk * gk.x, kb = k.y * rk * gk.y;

    const float QS = 0.125f * 1.4426950408889634f;  // 1/sqrt(D) * log2(e)
    float2 c = *(const float2*)(cosd + n * D_ + d0);
    float2 s = *(const float2*)(sind + n * D_ + d0);
    const float qo0 = (qa * c.x - qb * s.x) * QS;
    const float qo1 = (qb * c.y + qa * s.y) * QS;
    const float ko0 = ka * c.x - kb * s.x;
    const float ko1 = kb * c.y + ka * s.y;

    const int bh = b * H_ + w;
    const size_t qi = ((size_t)bh * N_ + n) * D_ + d0;
    *(__half2*)&g_qh[qi] = __floats2half2_rn(qo0, qo1);
    *(__half2*)&g_kh[qi] = __floats2half2_rn(ko0, ko1);
}

// =====================================================================
// V transpose: g_qkv v-part [b][n][h*64+d] -> g_vh [bh][d][n] fp16
// =====================================================================
__global__ void vtrans_kernel()
{
    __shared__ float t[64][65];
    const int bh = blockIdx.x;
    const int n0 = blockIdx.y * 64;
    const int b = bh >> 4, h = bh & 15;
    const int tid = threadIdx.x;

    for (int i = tid; i < 4096; i += 256) {
        const int r = i >> 6, c = i & 63;
        t[c][r] = g_qkv[((size_t)(b * N_ + n0 + r)) * (3 * C_) + 2 * C_ + h * 64 + c];
    }
    __syncthreads();
    for (int i = tid; i < 4096; i += 256) {
        const int d = i >> 6, n = i & 63;
        g_vh[((size_t)bh * D_ + d) * N_ + n0 + n] = __float2half_rn(t[d][n]);
    }
}

// =====================================================================
// Flash attention fp16: CTA = 256 q-rows, warp = 32 q-rows; K-tile = 64.
// smem: Q[256][64] fp16 32KB + 4 stages of (K 8KB | V 8KB) = 96KB.
// Single barrier per iteration. 32 iterations.
// =====================================================================
#define FSTG 16384
#define FLASH_SMEM (32768 + 4 * FSTG)

__global__ __launch_bounds__(256, 1)
void flash_mma(__half* __restrict__ outs)
{
    extern __shared__ char smem[];
    const uint32_t sb = smem_u32(smem);
    const int bh  = blockIdx.y;
    const int q0  = blockIdx.x * 256;
    const int tid = threadIdx.x;
    const int lane = tid & 31;
    const int wid  = tid >> 5;

    const __half* qhp = g_qh + (size_t)bh * N_ * D_;
    const __half* khp = g_kh + (size_t)bh * N_ * D_;
    const __half* vhp = g_vh + (size_t)bh * D_ * N_;

    // Q resident: 2048 chunks, 8 per thread
#pragma unroll
    for (int j = 0; j < 8; j++) {
        const int idx = tid + 256 * j;
        const int r = idx >> 3, c = idx & 7;
        const uint32_t so = (uint32_t)(r * 128 + ((c ^ (r & 7)) << 4));
        cpa16(sb + so, qhp + (size_t)(q0 + r) * D_ + c * 8);
    }

    // stage load descriptors: 1024 chunks (K 512 + V 512), 4 per thread
    uint32_t soff[4]; const __half* gp[4]; int gstride[4];
#pragma unroll
    for (int j = 0; j < 4; j++) {
        const int idx = tid + 256 * j;
        const int plane = idx >> 9;            // 0=K, 1=V
        const int r = (idx >> 3) & 63, c = idx & 7;
        soff[j] = (uint32_t)(plane * 8192 + r * 128 + ((c ^ (r & 7)) << 4));
        if (plane == 0) { gp[j] = khp + (size_t)r * D_ + c * 8; gstride[j] = 64 * D_; }
        else            { gp[j] = vhp + (size_t)r * N_ + c * 8; gstride[j] = 64; }
    }

    auto load_stage = [&](int buf, int kt) {
        const uint32_t st = sb + 32768 + buf * FSTG;
#pragma unroll
        for (int j = 0; j < 4; j++)
            cpa16(st + soff[j], gp[j] + (size_t)kt * gstride[j]);
        CP_COMMIT();
    };

    load_stage(0, 0);
    load_stage(1, 1);
    load_stage(2, 2);

    const int swz = lane & 7;
    const int cA = lane >> 4;
    const int cB = (lane >> 3) & 1;
    uint32_t aoff[2];
#pragma unroll
    for (int mt = 0; mt < 2; mt++)
        aoff[mt] = (uint32_t)((wid * 32 + mt * 16 + (lane & 15)) * 128);
    uint32_t boff[4];
#pragma unroll
    for (int nt = 0; nt < 4; nt++)
        boff[nt] = (uint32_t)((nt * 16 + ((lane >> 4) << 3) + (lane & 7)) * 128);

    float oc[2][8][4];
    float m_r[2][2], l_r[2][2];
#pragma unroll
    for (int mt = 0; mt < 2; mt++) {
#pragma unroll
        for (int i = 0; i < 8; i++)
#pragma unroll
            for (int j = 0; j < 4; j++) oc[mt][i][j] = 0.f;
        m_r[mt][0] = m_r[mt][1] = -1e30f;
        l_r[mt][0] = l_r[mt][1] = 0.f;
    }

    const int KTN = N_ / 64;   // 32
#pragma unroll 1
    for (int kt = 0; kt < KTN; kt++) {
        if (kt + 2 < KTN)      { CP_WAIT(2); }
        else if (kt + 1 < KTN) { CP_WAIT(1); }
        else                   { CP_WAIT(0); }
        __syncthreads();
        if (kt + 3 < KTN) load_stage((kt + 3) & 3, kt + 3);
        const uint32_t st = sb + 32768 + (kt & 3) * FSTG;

        // ---- S = Q K^T (64 keys), log2 units ----
        float sc[2][8][4];
#pragma unroll
        for (int mt = 0; mt < 2; mt++)
#pragma unroll
            for (int i = 0; i < 8; i++)
#pragma unroll
                for (int j = 0; j < 4; j++) sc[mt][i][j] = 0.f;

#pragma unroll
        for (int kk = 0; kk < 4; kk++) {
            const uint32_t swA = (uint32_t)(((kk * 2 + cA) ^ swz) << 4);
            const uint32_t swB = (uint32_t)(((kk * 2 + cB) ^ swz) << 4);
            uint32_t aq[2][4];
            ldm4(sb + aoff[0] + swA, aq[0]);
            ldm4(sb + aoff[1] + swA, aq[1]);
#pragma unroll
            for (int nt = 0; nt < 4; nt++) {
                uint32_t kh[4];
                ldm4(st + boff[nt] + swB, kh);
#pragma unroll
                for (int mt = 0; mt < 2; mt++)
#pragma unroll
                    for (int h = 0; h < 2; h++)
                        mma_f16(sc[mt][nt * 2 + h], aq[mt], &kh[h * 2]);
            }
        }

        // ---- online softmax (exp2) ----
#pragma unroll
        for (int mt = 0; mt < 2; mt++)
#pragma unroll
            for (int p = 0; p < 2; p++) {
                float mx = -1e30f;
#pragma unroll
                for (int ng = 0; ng < 8; ng++)
                    mx = fmaxf(mx, fmaxf(sc[mt][ng][2 * p], sc[mt][ng][2 * p + 1]));
                mx = fmaxf(mx, __shfl_xor_sync(0xffffffffu, mx, 1));
                mx = fmaxf(mx, __shfl_xor_sync(0xffffffffu, mx, 2));
                const float mnew = fmaxf(m_r[mt][p], mx);
                const float f = exp2f(m_r[mt][p] - mnew);
                m_r[mt][p] = mnew;
                float rs = 0.f;
#pragma unroll
                for (int ng = 0; ng < 8; ng++) {
                    sc[mt][ng][2 * p]     = exp2f(sc[mt][ng][2 * p] - mnew);
                    sc[mt][ng][2 * p + 1] = exp2f(sc[mt][ng][2 * p + 1] - mnew);
                    rs += sc[mt][ng][2 * p] + sc[mt][ng][2 * p + 1];
                }
                rs += __shfl_xor_sync(0xffffffffu, rs, 1);
                rs += __shfl_xor_sync(0xffffffffu, rs, 2);
                l_r[mt][p] = l_r[mt][p] * f + rs;
#pragma unroll
                for (int dt = 0; dt < 8; dt++) {
                    oc[mt][dt][2 * p] *= f;
                    oc[mt][dt][2 * p + 1] *= f;
                }
            }

        // ---- O += P V ----
#pragma unroll
        for (int kk = 0; kk < 4; kk++) {
            uint32_t ph[2][4];
#pragma unroll
            for (int mt = 0; mt < 2; mt++)
#pragma unroll
                for (int u = 0; u < 2; u++) {
                    const int ng = 2 * kk + u;
#pragma unroll
                    for (int v = 0; v < 2; v++) {
                        __half2 hh = __floats2half2_rn(sc[mt][ng][2 * v],
                                                       sc[mt][ng][2 * v + 1]);
                        ph[mt][u * 2 + v] = *(uint32_t*)&hh;
                    }
                }
            const uint32_t swV = (uint32_t)(((kk * 2 + cB) ^ swz) << 4);
#pragma unroll
            for (int nt = 0; nt < 4; nt++) {
                uint32_t vh[4];
                ldm4(st + 8192 + boff[nt] + swV, vh);
#pragma unroll
                for (int mt = 0; mt < 2; mt++)
#pragma unroll
                    for (int h2 = 0; h2 < 2; h2++)
                        mma_f16(oc[mt][nt * 2 + h2], ph[mt], &vh[h2 * 2]);
            }
        }
    }

    // ---- epilogue ----
    const int b = bh >> 4, h = bh & 15;
#pragma unroll
    for (int mt = 0; mt < 2; mt++)
#pragma unroll
        for (int p = 0; p < 2; p++) {
            const int n = q0 + wid * 32 + mt * 16 + (lane >> 2) + 8 * p;
            const float inv = 1.f / l_r[mt][p];
#pragma unroll
            for (int dt = 0; dt < 8; dt++) {
                const int d = dt * 8 + 2 * (lane & 3);
                const size_t oi = ((size_t)(b * N_ + n)) * C_ + h * D_ + d;
                *(__half2*)&outs[oi] = __floats2half2_rn(
                    oc[mt][dt][2 * p] * inv, oc[mt][dt][2 * p + 1] * inv);
            }
        }
}

// =====================================================================
extern "C" void kernel_launch(void* const* d_in, const int* in_sizes, int n_in,
                              void* d_out, int out_size)
{
    const float* x      = (const float*)d_in[0];
    const float* cosd   = (const float*)d_in[1];
    const float* sind   = (const float*)d_in[2];
    const float* w_qkv  = (const float*)d_in[3];
    const float* w_proj = (const float*)d_in[4];
    const float* q_gam  = (const float*)d_in[5];
    const float* k_gam  = (const float*)d_in[6];
    float* out = (float*)d_out;

    float* p_qkv = nullptr;
    __half *p_xh = nullptr, *p_wqkvh = nullptr, *p_atth = nullptr, *p_wprojh = nullptr;
    cudaGetSymbolAddress((void**)&p_qkv, g_qkv);
    cudaGetSymbolAddress((void**)&p_xh, g_xh);
    cudaGetSymbolAddress((void**)&p_wqkvh, g_wqkvh);
    cudaGetSymbolAddress((void**)&p_atth, g_atth);
    cudaGetSymbolAddress((void**)&p_wprojh, g_wprojh);

    const size_t n_x = (size_t)BN_ * C_;
    const size_t n_wqkv = (size_t)3 * C_ * C_;
    const size_t n_wproj = (size_t)C_ * C_;

    cudaFuncSetAttribute(gemm1_mma,
                         cudaFuncAttributeMaxDynamicSharedMemorySize, GSMEM1);
    cudaFuncSetAttribute(flash_mma,
                         cudaFuncAttributeMaxDynamicSharedMemorySize, FLASH_SMEM);

    // 1) splits: x, w_qkv, w_proj -> fp16
    splith_kernel<<<(int)(n_x / 4 / 256), 256>>>(x, p_xh, n_x);
    splith_kernel<<<(int)(n_wqkv / 4 / 256), 256>>>(w_qkv, p_wqkvh, n_wqkv);
    splith_kernel<<<(int)(n_wproj / 4 / 256), 256>>>(w_proj, p_wprojh, n_wproj);

    // 2) QKV projection (fp16 tensor cores, 64x64 warp tiles)
    gemm1_mma<<<dim3(3 * C_ / 256, BN_ / 128), 256, GSMEM1>>>(
        p_xh, p_wqkvh, p_qkv, 3 * C_, C_);

    // 3) RMSNorm + RoPE -> fp16; V transpose -> fp16
    prep_kernel<<<BN_, 512>>>(cosd, sind, q_gam, k_gam);
    vtrans_kernel<<<dim3(BH_, N_ / 64), 256>>>();

    // 4) flash attention (fp16, 256 q-rows/CTA)
    flash_mma<<<dim3(N_ / 256, BH_), 256, FLASH_SMEM>>>(p_atth);

    // 5) output projection
    gemm1_mma<<<dim3(C_ / 256, BN_ / 128), 256, GSMEM1>>>(
        p_atth, p_wprojh, out, C_, C_);
}

// round 11
// speedup vs baseline: 3.8853x; 1.0481x over previous
#include <cuda_runtime.h>
#include <cuda_bf16.h>
#include <cuda_fp16.h>
#include <cstdint>
#include <math.h>

#define B_  4
#define N_  2048
#define C_  1024
#define H_  16
#define D_  64
#define BH_ (B_ * H_)   // 64
#define BN_ (B_ * N_)   // 8192

// ---------------- scratch (device globals; no allocations allowed) ----------
__device__ __half g_xh[(size_t)BN_ * C_];                // x: fp16
__device__ __half g_wqkvh[(size_t)3 * C_ * C_];          // w_qkv: fp16
__device__ __half g_wprojh[(size_t)C_ * C_];             // w_proj: fp16
__device__ __half g_atth[(size_t)BN_ * C_];              // att: fp16
__device__ __half g_qh[(size_t)BH_ * N_ * D_];           // q: fp16, normed+roped+scaled
__device__ __half g_kh[(size_t)BH_ * N_ * D_];           // k: fp16, normed+roped
__device__ __half g_vnh[(size_t)BN_ * C_];               // v: fp16, [b][n][h*64+d]
__device__ __half g_vh[(size_t)BH_ * D_ * N_];           // v: fp16, [bh][d][n]

// =====================================================================
// helpers
// =====================================================================
__device__ __forceinline__ uint32_t smem_u32(const void* p) {
    uint32_t a;
    asm("{ .reg .u64 t; cvta.to.shared.u64 t, %1; cvt.u32.u64 %0, t; }"
        : "=r"(a) : "l"(p));
    return a;
}

__device__ __forceinline__ void cpa16(uint32_t s, const void* g) {
    asm volatile("cp.async.cg.shared.global [%0], [%1], 16;"
                 :: "r"(s), "l"(g) : "memory");
}
#define CP_COMMIT()  asm volatile("cp.async.commit_group;" ::: "memory")
#define CP_WAIT(n)   asm volatile("cp.async.wait_group %0;" :: "n"(n) : "memory")

__device__ __forceinline__ void ldm4(uint32_t addr, uint32_t* r) {
    asm volatile("ldmatrix.sync.aligned.m8n8.x4.shared.b16 {%0,%1,%2,%3}, [%4];"
                 : "=r"(r[0]), "=r"(r[1]), "=r"(r[2]), "=r"(r[3]) : "r"(addr));
}

__device__ __forceinline__ void mma_f16(float* c, const uint32_t* a, const uint32_t* b) {
    asm volatile(
        "mma.sync.aligned.m16n8k16.row.col.f32.f16.f16.f32 "
        "{%0,%1,%2,%3}, {%4,%5,%6,%7}, {%8,%9}, {%0,%1,%2,%3};"
        : "+f"(c[0]), "+f"(c[1]), "+f"(c[2]), "+f"(c[3])
        : "r"(a[0]), "r"(a[1]), "r"(a[2]), "r"(a[3]), "r"(b[0]), "r"(b[1]));
}

// fp32 -> fp16 (single rounded plane)
__global__ void splith_kernel(const float* __restrict__ src,
                              __half* __restrict__ dst, size_t n)
{
    size_t i = ((size_t)blockIdx.x * blockDim.x + threadIdx.x) * 4;
    if (i >= n) return;
    float4 v = *(const float4*)(src + i);
    __half2* hp = (__half2*)(dst + i);
    hp[0] = __floats2half2_rn(v.x, v.y);
    hp[1] = __floats2half2_rn(v.z, v.w);
}

// =====================================================================
// fp16 GEMM: CTA 128x256, warp tile 64x64, 4 stages, 1 barrier/iter.
// fuse==1: QKV mode. Warp's 64-col tile == one head slot t (0..47):
//   t<16 -> q head  : RMSNorm + gamma + RoPE + QS -> g_qh [bh][n][d] fp16
//   t<32 -> k head  : RMSNorm + gamma + RoPE       -> g_kh [bh][n][d] fp16
//   else -> v head  : fp16 -> g_vnh [b*n][h*64+d]
// fuse==0: plain fp32 store to C (proj).
// =====================================================================
#define STG1 49152
#define GSMEM1 (4 * STG1)
__global__ __launch_bounds__(256, 1)
void gemm1_mma(const __half* __restrict__ A, const __half* __restrict__ Bm,
               float* __restrict__ C, int ldC, int K, int fuse,
               const float* __restrict__ cosd, const float* __restrict__ sind,
               const float* __restrict__ qgam, const float* __restrict__ kgam)
{
    extern __shared__ char smem[];
    const uint32_t sb = smem_u32(smem);
    const int tid  = threadIdx.x;
    const int lane = tid & 31;
    const int wid  = tid >> 5;
    const int m0 = blockIdx.y * 128;
    const int n0 = blockIdx.x * 256;
    const int wm = (wid >> 2) * 64;
    const int wn = (wid & 3) * 64;

    uint32_t sA[4]; const __half* pA[4];
#pragma unroll
    for (int j = 0; j < 4; j++) {
        const int idx = tid + 256 * j;
        const int r = idx >> 3, c = idx & 7;
        sA[j] = (uint32_t)(r * 128 + ((c ^ (r & 7)) << 4));
        pA[j] = A + (size_t)(m0 + r) * K + c * 8;
    }
    uint32_t sB[8]; const __half* pB[8];
#pragma unroll
    for (int j = 0; j < 8; j++) {
        const int idx = tid + 256 * j;
        const int r = idx >> 3, c = idx & 7;
        sB[j] = (uint32_t)(16384 + r * 128 + ((c ^ (r & 7)) << 4));
        pB[j] = Bm + (size_t)(n0 + r) * K + c * 8;
    }

    uint32_t arow[4], brow[4];
#pragma unroll
    for (int mt = 0; mt < 4; mt++)
        arow[mt] = (uint32_t)((wm + mt * 16 + (lane & 15)) * 128);
#pragma unroll
    for (int nt = 0; nt < 4; nt++)
        brow[nt] = (uint32_t)(16384 +
            (wn + nt * 16 + ((lane >> 4) << 3) + (lane & 7)) * 128);
    const int swz = lane & 7;
    const int cA = lane >> 4;
    const int cB = (lane >> 3) & 1;

    float acc[4][8][4];
#pragma unroll
    for (int i = 0; i < 4; i++)
#pragma unroll
        for (int j = 0; j < 8; j++)
#pragma unroll
            for (int r = 0; r < 4; r++) acc[i][j][r] = 0.f;

    const int KT = K >> 6;

    auto load_stage = [&](int buf, int kt) {
        const uint32_t st = sb + buf * STG1;
        const int k0 = kt * 64;
#pragma unroll
        for (int j = 0; j < 4; j++) cpa16(st + sA[j], pA[j] + k0);
#pragma unroll
        for (int j = 0; j < 8; j++) cpa16(st + sB[j], pB[j] + k0);
        CP_COMMIT();
    };

    load_stage(0, 0);
    load_stage(1, 1);
    load_stage(2, 2);

#pragma unroll 1
    for (int kt = 0; kt < KT; kt++) {
        if (kt + 2 < KT)      { CP_WAIT(2); }
        else if (kt + 1 < KT) { CP_WAIT(1); }
        else                  { CP_WAIT(0); }
        __syncthreads();
        if (kt + 3 < KT) load_stage((kt + 3) & 3, kt + 3);

        const uint32_t st = sb + (kt & 3) * STG1;
#pragma unroll
        for (int kk = 0; kk < 4; kk++) {
            uint32_t ah[4][4], bh[4][4];
            const uint32_t swA = (uint32_t)(((kk * 2 + cA) ^ swz) << 4);
            const uint32_t swB = (uint32_t)(((kk * 2 + cB) ^ swz) << 4);
#pragma unroll
            for (int mt = 0; mt < 4; mt++) ldm4(st + arow[mt] + swA, ah[mt]);
#pragma unroll
            for (int nt = 0; nt < 4; nt++) ldm4(st + brow[nt] + swB, bh[nt]);
#pragma unroll
            for (int mt = 0; mt < 4; mt++)
#pragma unroll
                for (int nt = 0; nt < 4; nt++)
#pragma unroll
                    for (int h = 0; h < 2; h++)
                        mma_f16(acc[mt][nt * 2 + h], ah[mt], &bh[nt][h * 2]);
        }
    }

    const int g = lane >> 2, tg = lane & 3;

    if (!fuse) {
#pragma unroll
        for (int mt = 0; mt < 4; mt++)
#pragma unroll
            for (int ng = 0; ng < 8; ng++) {
                const int row = m0 + wm + mt * 16 + g;
                const int col = n0 + wn + ng * 8 + tg * 2;
                *(float2*)&C[(size_t)row * ldC + col] =
                    make_float2(acc[mt][ng][0], acc[mt][ng][1]);
                *(float2*)&C[(size_t)(row + 8) * ldC + col] =
                    make_float2(acc[mt][ng][2], acc[mt][ng][3]);
            }
        return;
    }

    // ---- fused QKV epilogue ----
    const int t = (n0 + wn) >> 6;          // head slot 0..47 (warp-uniform)
    const float QS = 0.125f * 1.4426950408889634f;

#pragma unroll
    for (int mt = 0; mt < 4; mt++) {
#pragma unroll
        for (int half = 0; half < 2; half++) {
            const int row = m0 + wm + mt * 16 + g + half * 8;   // token index
            const int n = row & (N_ - 1);
            const int b = row >> 11;
            if (t >= 32) {
                // V head: plain fp16 store to [b*n][h*64+d]
                const int hv = t - 32;
#pragma unroll
                for (int ng = 0; ng < 8; ng++) {
                    const int d = ng * 8 + tg * 2;
                    *(__half2*)&g_vnh[(size_t)row * C_ + hv * D_ + d] =
                        __floats2half2_rn(acc[mt][ng][2 * half],
                                          acc[mt][ng][2 * half + 1]);
                }
            } else {
                // q or k head: RMSNorm over the 64 cols of this warp tile
                float ss = 0.f;
#pragma unroll
                for (int ng = 0; ng < 8; ng++) {
                    const float v0 = acc[mt][ng][2 * half];
                    const float v1 = acc[mt][ng][2 * half + 1];
                    ss += v0 * v0 + v1 * v1;
                }
                ss += __shfl_xor_sync(0xffffffffu, ss, 1);
                ss += __shfl_xor_sync(0xffffffffu, ss, 2);
                const float rn = rsqrtf(ss * (1.f / 64.f) + 1e-6f);
                const int isq = (t < 16);
                const float* gam = isq ? qgam : kgam;
                const int h = t & 15;
                const int bh = b * H_ + h;
                __half* dst = (isq ? g_qh : g_kh) + ((size_t)bh * N_ + n) * D_;
#pragma unroll
                for (int ng = 0; ng < 8; ng++) {
                    const int d = ng * 8 + tg * 2;
                    const float2 gm = *(const float2*)(gam + d);
                    const float2 c = *(const float2*)(cosd + n * D_ + d);
                    const float2 s = *(const float2*)(sind + n * D_ + d);
                    const float a0 = acc[mt][ng][2 * half] * rn * gm.x;
                    const float a1 = acc[mt][ng][2 * half + 1] * rn * gm.y;
                    float o0 = a0 * c.x - a1 * s.x;
                    float o1 = a1 * c.y + a0 * s.y;
                    if (isq) { o0 *= QS; o1 *= QS; }
                    *(__half2*)&dst[d] = __floats2half2_rn(o0, o1);
                }
            }
        }
    }
}

// =====================================================================
// V transpose: g_vnh [b][n][h*64+d] fp16 -> g_vh [bh][d][n] fp16
// =====================================================================
__global__ void vtrans_kernel()
{
    __shared__ float t[64][65];
    const int bh = blockIdx.x;
    const int n0 = blockIdx.y * 64;
    const int b = bh >> 4, h = bh & 15;
    const int tid = threadIdx.x;

    for (int i = tid; i < 4096; i += 256) {
        const int r = i >> 6, c = i & 63;
        t[c][r] = __half2float(
            g_vnh[((size_t)(b * N_ + n0 + r)) * C_ + h * D_ + c]);
    }
    __syncthreads();
    for (int i = tid; i < 4096; i += 256) {
        const int d = i >> 6, n = i & 63;
        g_vh[((size_t)bh * D_ + d) * N_ + n0 + n] = __float2half_rn(t[d][n]);
    }
}

// =====================================================================
// Flash attention fp16: CTA = 256 q-rows, warp = 32 q-rows; K-tile = 64.
// smem: Q[256][64] fp16 32KB + 4 stages of (K 8KB | V 8KB) = 96KB.
// =====================================================================
#define FSTG 16384
#define FLASH_SMEM (32768 + 4 * FSTG)

__global__ __launch_bounds__(256, 1)
void flash_mma(__half* __restrict__ outs)
{
    extern __shared__ char smem[];
    const uint32_t sb = smem_u32(smem);
    const int bh  = blockIdx.y;
    const int q0  = blockIdx.x * 256;
    const int tid = threadIdx.x;
    const int lane = tid & 31;
    const int wid  = tid >> 5;

    const __half* qhp = g_qh + (size_t)bh * N_ * D_;
    const __half* khp = g_kh + (size_t)bh * N_ * D_;
    const __half* vhp = g_vh + (size_t)bh * D_ * N_;

#pragma unroll
    for (int j = 0; j < 8; j++) {
        const int idx = tid + 256 * j;
        const int r = idx >> 3, c = idx & 7;
        const uint32_t so = (uint32_t)(r * 128 + ((c ^ (r & 7)) << 4));
        cpa16(sb + so, qhp + (size_t)(q0 + r) * D_ + c * 8);
    }

    uint32_t soff[4]; const __half* gp[4]; int gstride[4];
#pragma unroll
    for (int j = 0; j < 4; j++) {
        const int idx = tid + 256 * j;
        const int plane = idx >> 9;            // 0=K, 1=V
        const int r = (idx >> 3) & 63, c = idx & 7;
        soff[j] = (uint32_t)(plane * 8192 + r * 128 + ((c ^ (r & 7)) << 4));
        if (plane == 0) { gp[j] = khp + (size_t)r * D_ + c * 8; gstride[j] = 64 * D_; }
        else            { gp[j] = vhp + (size_t)r * N_ + c * 8; gstride[j] = 64; }
    }

    auto load_stage = [&](int buf, int kt) {
        const uint32_t st = sb + 32768 + buf * FSTG;
#pragma unroll
        for (int j = 0; j < 4; j++)
            cpa16(st + soff[j], gp[j] + (size_t)kt * gstride[j]);
        CP_COMMIT();
    };

    load_stage(0, 0);
    load_stage(1, 1);
    load_stage(2, 2);

    const int swz = lane & 7;
    const int cA = lane >> 4;
    const int cB = (lane >> 3) & 1;
    uint32_t aoff[2];
#pragma unroll
    for (int mt = 0; mt < 2; mt++)
        aoff[mt] = (uint32_t)((wid * 32 + mt * 16 + (lane & 15)) * 128);
    uint32_t boff[4];
#pragma unroll
    for (int nt = 0; nt < 4; nt++)
        boff[nt] = (uint32_t)((nt * 16 + ((lane >> 4) << 3) + (lane & 7)) * 128);

    float oc[2][8][4];
    float m_r[2][2], l_r[2][2];
#pragma unroll
    for (int mt = 0; mt < 2; mt++) {
#pragma unroll
        for (int i = 0; i < 8; i++)
#pragma unroll
            for (int j = 0; j < 4; j++) oc[mt][i][j] = 0.f;
        m_r[mt][0] = m_r[mt][1] = -1e30f;
        l_r[mt][0] = l_r[mt][1] = 0.f;
    }

    const int KTN = N_ / 64;   // 32
#pragma unroll 1
    for (int kt = 0; kt < KTN; kt++) {
        if (kt + 2 < KTN)      { CP_WAIT(2); }
        else if (kt + 1 < KTN) { CP_WAIT(1); }
        else                   { CP_WAIT(0); }
        __syncthreads();
        if (kt + 3 < KTN) load_stage((kt + 3) & 3, kt + 3);
        const uint32_t st = sb + 32768 + (kt & 3) * FSTG;

        float sc[2][8][4];
#pragma unroll
        for (int mt = 0; mt < 2; mt++)
#pragma unroll
            for (int i = 0; i < 8; i++)
#pragma unroll
                for (int j = 0; j < 4; j++) sc[mt][i][j] = 0.f;

#pragma unroll
        for (int kk = 0; kk < 4; kk++) {
            const uint32_t swA = (uint32_t)(((kk * 2 + cA) ^ swz) << 4);
            const uint32_t swB = (uint32_t)(((kk * 2 + cB) ^ swz) << 4);
            uint32_t aq[2][4];
            ldm4(sb + aoff[0] + swA, aq[0]);
            ldm4(sb + aoff[1] + swA, aq[1]);
#pragma unroll
            for (int nt = 0; nt < 4; nt++) {
                uint32_t kh[4];
                ldm4(st + boff[nt] + swB, kh);
#pragma unroll
                for (int mt = 0; mt < 2; mt++)
#pragma unroll
                    for (int h = 0; h < 2; h++)
                        mma_f16(sc[mt][nt * 2 + h], aq[mt], &kh[h * 2]);
            }
        }

#pragma unroll
        for (int mt = 0; mt < 2; mt++)
#pragma unroll
            for (int p = 0; p < 2; p++) {
                float mx = -1e30f;
#pragma unroll
                for (int ng = 0; ng < 8; ng++)
                    mx = fmaxf(mx, fmaxf(sc[mt][ng][2 * p], sc[mt][ng][2 * p + 1]));
                mx = fmaxf(mx, __shfl_xor_sync(0xffffffffu, mx, 1));
                mx = fmaxf(mx, __shfl_xor_sync(0xffffffffu, mx, 2));
                const float mnew = fmaxf(m_r[mt][p], mx);
                const float f = exp2f(m_r[mt][p] - mnew);
                m_r[mt][p] = mnew;
                float rs = 0.f;
#pragma unroll
                for (int ng = 0; ng < 8; ng++) {
                    sc[mt][ng][2 * p]     = exp2f(sc[mt][ng][2 * p] - mnew);
                    sc[mt][ng][2 * p + 1] = exp2f(sc[mt][ng][2 * p + 1] - mnew);
                    rs += sc[mt][ng][2 * p] + sc[mt][ng][2 * p + 1];
                }
                rs += __shfl_xor_sync(0xffffffffu, rs, 1);
                rs += __shfl_xor_sync(0xffffffffu, rs, 2);
                l_r[mt][p] = l_r[mt][p] * f + rs;
#pragma unroll
                for (int dt = 0; dt < 8; dt++) {
                    oc[mt][dt][2 * p] *= f;
                    oc[mt][dt][2 * p + 1] *= f;
                }
            }

#pragma unroll
        for (int kk = 0; kk < 4; kk++) {
            uint32_t ph[2][4];
#pragma unroll
            for (int mt = 0; mt < 2; mt++)
#pragma unroll
                for (int u = 0; u < 2; u++) {
                    const int ng = 2 * kk + u;
#pragma unroll
                    for (int v = 0; v < 2; v++) {
                        __half2 hh = __floats2half2_rn(sc[mt][ng][2 * v],
                                                       sc[mt][ng][2 * v + 1]);
                        ph[mt][u * 2 + v] = *(uint32_t*)&hh;
                    }
                }
            const uint32_t swV = (uint32_t)(((kk * 2 + cB) ^ swz) << 4);
#pragma unroll
            for (int nt = 0; nt < 4; nt++) {
                uint32_t vh[4];
                ldm4(st + 8192 + boff[nt] + swV, vh);
#pragma unroll
                for (int mt = 0; mt < 2; mt++)
#pragma unroll
                    for (int h2 = 0; h2 < 2; h2++)
                        mma_f16(oc[mt][nt * 2 + h2], ph[mt], &vh[h2 * 2]);
            }
        }
    }

    const int b = bh >> 4, h = bh & 15;
#pragma unroll
    for (int mt = 0; mt < 2; mt++)
#pragma unroll
        for (int p = 0; p < 2; p++) {
            const int n = q0 + wid * 32 + mt * 16 + (lane >> 2) + 8 * p;
            const float inv = 1.f / l_r[mt][p];
#pragma unroll
            for (int dt = 0; dt < 8; dt++) {
                const int d = dt * 8 + 2 * (lane & 3);
                const size_t oi = ((size_t)(b * N_ + n)) * C_ + h * D_ + d;
                *(__half2*)&outs[oi] = __floats2half2_rn(
                    oc[mt][dt][2 * p] * inv, oc[mt][dt][2 * p + 1] * inv);
            }
        }
}

// =====================================================================
extern "C" void kernel_launch(void* const* d_in, const int* in_sizes, int n_in,
                              void* d_out, int out_size)
{
    const float* x      = (const float*)d_in[0];
    const float* cosd   = (const float*)d_in[1];
    const float* sind   = (const float*)d_in[2];
    const float* w_qkv  = (const float*)d_in[3];
    const float* w_proj = (const float*)d_in[4];
    const float* q_gam  = (const float*)d_in[5];
    const float* k_gam  = (const float*)d_in[6];
    float* out = (float*)d_out;

    __half *p_xh = nullptr, *p_wqkvh = nullptr, *p_atth = nullptr, *p_wprojh = nullptr;
    cudaGetSymbolAddress((void**)&p_xh, g_xh);
    cudaGetSymbolAddress((void**)&p_wqkvh, g_wqkvh);
    cudaGetSymbolAddress((void**)&p_atth, g_atth);
    cudaGetSymbolAddress((void**)&p_wprojh, g_wprojh);

    const size_t n_x = (size_t)BN_ * C_;
    const size_t n_wqkv = (size_t)3 * C_ * C_;
    const size_t n_wproj = (size_t)C_ * C_;

    cudaFuncSetAttribute(gemm1_mma,
                         cudaFuncAttributeMaxDynamicSharedMemorySize, GSMEM1);
    cudaFuncSetAttribute(flash_mma,
                         cudaFuncAttributeMaxDynamicSharedMemorySize, FLASH_SMEM);

    // 1) splits: x, w_qkv, w_proj -> fp16
    splith_kernel<<<(int)(n_x / 4 / 256), 256>>>(x, p_xh, n_x);
    splith_kernel<<<(int)(n_wqkv / 4 / 256), 256>>>(w_qkv, p_wqkvh, n_wqkv);
    splith_kernel<<<(int)(n_wproj / 4 / 256), 256>>>(w_proj, p_wprojh, n_wproj);

    // 2) QKV projection + fused RMSNorm/RoPE/layout epilogue
    gemm1_mma<<<dim3(3 * C_ / 256, BN_ / 128), 256, GSMEM1>>>(
        p_xh, p_wqkvh, nullptr, 3 * C_, C_, 1, cosd, sind, q_gam, k_gam);

    // 3) V transpose (fp16 in, fp16 out)
    vtrans_kernel<<<dim3(BH_, N_ / 64), 256>>>();

    // 4) flash attention
    flash_mma<<<dim3(N_ / 256, BH_), 256, FLASH_SMEM>>>(p_atth);

    // 5) output projection (plain fp32 epilogue)
    gemm1_mma<<<dim3(C_ / 256, BN_ / 128), 256, GSMEM1>>>(
        p_atth, p_wprojh, out, C_, C_, 0, nullptr, nullptr, nullptr, nullptr);
}

// round 12
// speedup vs baseline: 4.0333x; 1.0381x over previous
#include <cuda_runtime.h>
#include <cuda_bf16.h>
#include <cuda_fp16.h>
#include <cstdint>
#include <math.h>

#define B_  4
#define N_  2048
#define C_  1024
#define H_  16
#define D_  64
#define BH_ (B_ * H_)   // 64
#define BN_ (B_ * N_)   // 8192

// ---------------- scratch (device globals; no allocations allowed) ----------
__device__ __half g_xh[(size_t)BN_ * C_];                // x: fp16
__device__ __half g_wqkvh[(size_t)3 * C_ * C_];          // w_qkv: fp16
__device__ __half g_wprojh[(size_t)C_ * C_];             // w_proj: fp16
__device__ __half g_atth[(size_t)BN_ * C_];              // att: fp16
__device__ __half g_qh[(size_t)BH_ * N_ * D_];           // q: fp16, normed+roped+scaled
__device__ __half g_kh[(size_t)BH_ * N_ * D_];           // k: fp16, normed+roped
__device__ __half g_vnh[(size_t)BN_ * C_];               // v: fp16, [b][n][h*64+d]

// =====================================================================
// helpers
// =====================================================================
__device__ __forceinline__ uint32_t smem_u32(const void* p) {
    uint32_t a;
    asm("{ .reg .u64 t; cvta.to.shared.u64 t, %1; cvt.u32.u64 %0, t; }"
        : "=r"(a) : "l"(p));
    return a;
}

__device__ __forceinline__ void cpa16(uint32_t s, const void* g) {
    asm volatile("cp.async.cg.shared.global [%0], [%1], 16;"
                 :: "r"(s), "l"(g) : "memory");
}
#define CP_COMMIT()  asm volatile("cp.async.commit_group;" ::: "memory")
#define CP_WAIT(n)   asm volatile("cp.async.wait_group %0;" :: "n"(n) : "memory")

__device__ __forceinline__ void ldm4(uint32_t addr, uint32_t* r) {
    asm volatile("ldmatrix.sync.aligned.m8n8.x4.shared.b16 {%0,%1,%2,%3}, [%4];"
                 : "=r"(r[0]), "=r"(r[1]), "=r"(r[2]), "=r"(r[3]) : "r"(addr));
}

__device__ __forceinline__ void ldm4t(uint32_t addr, uint32_t* r) {
    asm volatile("ldmatrix.sync.aligned.m8n8.x4.trans.shared.b16 {%0,%1,%2,%3}, [%4];"
                 : "=r"(r[0]), "=r"(r[1]), "=r"(r[2]), "=r"(r[3]) : "r"(addr));
}

__device__ __forceinline__ void mma_f16(float* c, const uint32_t* a, const uint32_t* b) {
    asm volatile(
        "mma.sync.aligned.m16n8k16.row.col.f32.f16.f16.f32 "
        "{%0,%1,%2,%3}, {%4,%5,%6,%7}, {%8,%9}, {%0,%1,%2,%3};"
        : "+f"(c[0]), "+f"(c[1]), "+f"(c[2]), "+f"(c[3])
        : "r"(a[0]), "r"(a[1]), "r"(a[2]), "r"(a[3]), "r"(b[0]), "r"(b[1]));
}

// =====================================================================
// fused fp32 -> fp16 split of x, w_qkv, w_proj (one launch)
// =====================================================================
#define NX_   ((size_t)BN_ * C_)          // 8M
#define NWQ_  ((size_t)3 * C_ * C_)       // 3M
#define NWP_  ((size_t)C_ * C_)           // 1M
__global__ void splitall_kernel(const float* __restrict__ x,
                                const float* __restrict__ wq,
                                const float* __restrict__ wp)
{
    size_t i = ((size_t)blockIdx.x * blockDim.x + threadIdx.x) * 4;
    const float* src;
    __half* dst;
    if (i < NX_)                { src = x + i;               dst = g_xh + i; }
    else if (i < NX_ + NWQ_)    { src = wq + (i - NX_);      dst = g_wqkvh + (i - NX_); }
    else if (i < NX_ + NWQ_ + NWP_) {
        src = wp + (i - NX_ - NWQ_);
        dst = g_wprojh + (i - NX_ - NWQ_);
    } else return;
    float4 v = *(const float4*)src;
    __half2* hp = (__half2*)dst;
    hp[0] = __floats2half2_rn(v.x, v.y);
    hp[1] = __floats2half2_rn(v.z, v.w);
}

// =====================================================================
// fp16 GEMM: CTA 128x256, warp tile 64x64, 4 stages, 1 barrier/iter.
// fuse==1: QKV mode (RMSNorm+RoPE epilogue, fp16 q/k/v outputs).
// fuse==0: plain fp32 store to C (proj).
// =====================================================================
#define STG1 49152
#define GSMEM1 (4 * STG1)
__global__ __launch_bounds__(256, 1)
void gemm1_mma(const __half* __restrict__ A, const __half* __restrict__ Bm,
               float* __restrict__ C, int ldC, int K, int fuse,
               const float* __restrict__ cosd, const float* __restrict__ sind,
               const float* __restrict__ qgam, const float* __restrict__ kgam)
{
    extern __shared__ char smem[];
    const uint32_t sb = smem_u32(smem);
    const int tid  = threadIdx.x;
    const int lane = tid & 31;
    const int wid  = tid >> 5;
    const int m0 = blockIdx.y * 128;
    const int n0 = blockIdx.x * 256;
    const int wm = (wid >> 2) * 64;
    const int wn = (wid & 3) * 64;

    uint32_t sA[4]; const __half* pA[4];
#pragma unroll
    for (int j = 0; j < 4; j++) {
        const int idx = tid + 256 * j;
        const int r = idx >> 3, c = idx & 7;
        sA[j] = (uint32_t)(r * 128 + ((c ^ (r & 7)) << 4));
        pA[j] = A + (size_t)(m0 + r) * K + c * 8;
    }
    uint32_t sB[8]; const __half* pB[8];
#pragma unroll
    for (int j = 0; j < 8; j++) {
        const int idx = tid + 256 * j;
        const int r = idx >> 3, c = idx & 7;
        sB[j] = (uint32_t)(16384 + r * 128 + ((c ^ (r & 7)) << 4));
        pB[j] = Bm + (size_t)(n0 + r) * K + c * 8;
    }

    uint32_t arow[4], brow[4];
#pragma unroll
    for (int mt = 0; mt < 4; mt++)
        arow[mt] = (uint32_t)((wm + mt * 16 + (lane & 15)) * 128);
#pragma unroll
    for (int nt = 0; nt < 4; nt++)
        brow[nt] = (uint32_t)(16384 +
            (wn + nt * 16 + ((lane >> 4) << 3) + (lane & 7)) * 128);
    const int swz = lane & 7;
    const int cA = lane >> 4;
    const int cB = (lane >> 3) & 1;

    float acc[4][8][4];
#pragma unroll
    for (int i = 0; i < 4; i++)
#pragma unroll
        for (int j = 0; j < 8; j++)
#pragma unroll
            for (int r = 0; r < 4; r++) acc[i][j][r] = 0.f;

    const int KT = K >> 6;

    auto load_stage = [&](int buf, int kt) {
        const uint32_t st = sb + buf * STG1;
        const int k0 = kt * 64;
#pragma unroll
        for (int j = 0; j < 4; j++) cpa16(st + sA[j], pA[j] + k0);
#pragma unroll
        for (int j = 0; j < 8; j++) cpa16(st + sB[j], pB[j] + k0);
        CP_COMMIT();
    };

    load_stage(0, 0);
    load_stage(1, 1);
    load_stage(2, 2);

#pragma unroll 1
    for (int kt = 0; kt < KT; kt++) {
        if (kt + 2 < KT)      { CP_WAIT(2); }
        else if (kt + 1 < KT) { CP_WAIT(1); }
        else                  { CP_WAIT(0); }
        __syncthreads();
        if (kt + 3 < KT) load_stage((kt + 3) & 3, kt + 3);

        const uint32_t st = sb + (kt & 3) * STG1;
#pragma unroll
        for (int kk = 0; kk < 4; kk++) {
            uint32_t ah[4][4], bh[4][4];
            const uint32_t swA = (uint32_t)(((kk * 2 + cA) ^ swz) << 4);
            const uint32_t swB = (uint32_t)(((kk * 2 + cB) ^ swz) << 4);
#pragma unroll
            for (int mt = 0; mt < 4; mt++) ldm4(st + arow[mt] + swA, ah[mt]);
#pragma unroll
            for (int nt = 0; nt < 4; nt++) ldm4(st + brow[nt] + swB, bh[nt]);
#pragma unroll
            for (int mt = 0; mt < 4; mt++)
#pragma unroll
                for (int nt = 0; nt < 4; nt++)
#pragma unroll
                    for (int h = 0; h < 2; h++)
                        mma_f16(acc[mt][nt * 2 + h], ah[mt], &bh[nt][h * 2]);
        }
    }

    const int g = lane >> 2, tg = lane & 3;

    if (!fuse) {
#pragma unroll
        for (int mt = 0; mt < 4; mt++)
#pragma unroll
            for (int ng = 0; ng < 8; ng++) {
                const int row = m0 + wm + mt * 16 + g;
                const int col = n0 + wn + ng * 8 + tg * 2;
                *(float2*)&C[(size_t)row * ldC + col] =
                    make_float2(acc[mt][ng][0], acc[mt][ng][1]);
                *(float2*)&C[(size_t)(row + 8) * ldC + col] =
                    make_float2(acc[mt][ng][2], acc[mt][ng][3]);
            }
        return;
    }

    // ---- fused QKV epilogue ----
    const int t = (n0 + wn) >> 6;          // head slot 0..47 (warp-uniform)
    const float QS = 0.125f * 1.4426950408889634f;

#pragma unroll
    for (int mt = 0; mt < 4; mt++) {
#pragma unroll
        for (int half = 0; half < 2; half++) {
            const int row = m0 + wm + mt * 16 + g + half * 8;   // token index
            const int n = row & (N_ - 1);
            const int b = row >> 11;
            if (t >= 32) {
                const int hv = t - 32;
#pragma unroll
                for (int ng = 0; ng < 8; ng++) {
                    const int d = ng * 8 + tg * 2;
                    *(__half2*)&g_vnh[(size_t)row * C_ + hv * D_ + d] =
                        __floats2half2_rn(acc[mt][ng][2 * half],
                                          acc[mt][ng][2 * half + 1]);
                }
            } else {
                float ss = 0.f;
#pragma unroll
                for (int ng = 0; ng < 8; ng++) {
                    const float v0 = acc[mt][ng][2 * half];
                    const float v1 = acc[mt][ng][2 * half + 1];
                    ss += v0 * v0 + v1 * v1;
                }
                ss += __shfl_xor_sync(0xffffffffu, ss, 1);
                ss += __shfl_xor_sync(0xffffffffu, ss, 2);
                const float rn = rsqrtf(ss * (1.f / 64.f) + 1e-6f);
                const int isq = (t < 16);
                const float* gam = isq ? qgam : kgam;
                const int h = t & 15;
                const int bh = b * H_ + h;
                __half* dst = (isq ? g_qh : g_kh) + ((size_t)bh * N_ + n) * D_;
#pragma unroll
                for (int ng = 0; ng < 8; ng++) {
                    const int d = ng * 8 + tg * 2;
                    const float2 gm = *(const float2*)(gam + d);
                    const float2 c = *(const float2*)(cosd + n * D_ + d);
                    const float2 s = *(const float2*)(sind + n * D_ + d);
                    const float a0 = acc[mt][ng][2 * half] * rn * gm.x;
                    const float a1 = acc[mt][ng][2 * half + 1] * rn * gm.y;
                    float o0 = a0 * c.x - a1 * s.x;
                    float o1 = a1 * c.y + a0 * s.y;
                    if (isq) { o0 *= QS; o1 *= QS; }
                    *(__half2*)&dst[d] = __floats2half2_rn(o0, o1);
                }
            }
        }
    }
}

// =====================================================================
// Flash attention fp16: CTA = 256 q-rows, warp = 32 q-rows; K-tile = 64.
// V consumed row-major [s][d] from g_vnh via ldmatrix.trans (no vtrans).
// smem: Q[256][64] 32KB + 4 stages of (K 8KB | V 8KB) = 96KB.
// =====================================================================
#define FSTG 16384
#define FLASH_SMEM (32768 + 4 * FSTG)

__global__ __launch_bounds__(256, 1)
void flash_mma(__half* __restrict__ outs)
{
    extern __shared__ char smem[];
    const uint32_t sb = smem_u32(smem);
    const int bh  = blockIdx.y;
    const int q0  = blockIdx.x * 256;
    const int tid = threadIdx.x;
    const int lane = tid & 31;
    const int wid  = tid >> 5;
    const int bb = bh >> 4, hh = bh & 15;

    const __half* qhp = g_qh + (size_t)bh * N_ * D_;
    const __half* khp = g_kh + (size_t)bh * N_ * D_;
    const __half* vhp = g_vnh + (size_t)(bb * N_) * C_ + hh * D_;  // row stride C_

#pragma unroll
    for (int j = 0; j < 8; j++) {
        const int idx = tid + 256 * j;
        const int r = idx >> 3, c = idx & 7;
        const uint32_t so = (uint32_t)(r * 128 + ((c ^ (r & 7)) << 4));
        cpa16(sb + so, qhp + (size_t)(q0 + r) * D_ + c * 8);
    }

    // stage chunks: K 512 + V 512, 4 per thread. Both [s][d] row-major.
    uint32_t soff[4]; const __half* gp[4]; size_t gstride[4];
#pragma unroll
    for (int j = 0; j < 4; j++) {
        const int idx = tid + 256 * j;
        const int plane = idx >> 9;            // 0=K, 1=V
        const int r = (idx >> 3) & 63, c = idx & 7;
        soff[j] = (uint32_t)(plane * 8192 + r * 128 + ((c ^ (r & 7)) << 4));
        if (plane == 0) { gp[j] = khp + (size_t)r * D_ + c * 8; gstride[j] = (size_t)64 * D_; }
        else            { gp[j] = vhp + (size_t)r * C_ + c * 8; gstride[j] = (size_t)64 * C_; }
    }

    auto load_stage = [&](int buf, int kt) {
        const uint32_t st = sb + 32768 + buf * FSTG;
#pragma unroll
        for (int j = 0; j < 4; j++)
            cpa16(st + soff[j], gp[j] + (size_t)kt * gstride[j]);
        CP_COMMIT();
    };

    load_stage(0, 0);
    load_stage(1, 1);
    load_stage(2, 2);

    const int swz = lane & 7;
    const int cA = lane >> 4;
    const int cB = (lane >> 3) & 1;
    uint32_t aoff[2];
#pragma unroll
    for (int mt = 0; mt < 2; mt++)
        aoff[mt] = (uint32_t)((wid * 32 + mt * 16 + (lane & 15)) * 128);
    uint32_t boff[4];
#pragma unroll
    for (int nt = 0; nt < 4; nt++)
        boff[nt] = (uint32_t)((nt * 16 + ((lane >> 4) << 3) + (lane & 7)) * 128);

    // V trans-load per-lane constants: s-row within 16-row chunk, d-chunk half
    const int vs = (lane & 7) + ((lane >> 3) & 1) * 8;   // 0..15
    const int vd = lane >> 4;                            // 0/1

    float oc[2][8][4];
    float m_r[2][2], l_r[2][2];
#pragma unroll
    for (int mt = 0; mt < 2; mt++) {
#pragma unroll
        for (int i = 0; i < 8; i++)
#pragma unroll
            for (int j = 0; j < 4; j++) oc[mt][i][j] = 0.f;
        m_r[mt][0] = m_r[mt][1] = -1e30f;
        l_r[mt][0] = l_r[mt][1] = 0.f;
    }

    const int KTN = N_ / 64;   // 32
#pragma unroll 1
    for (int kt = 0; kt < KTN; kt++) {
        if (kt + 2 < KTN)      { CP_WAIT(2); }
        else if (kt + 1 < KTN) { CP_WAIT(1); }
        else                   { CP_WAIT(0); }
        __syncthreads();
        if (kt + 3 < KTN) load_stage((kt + 3) & 3, kt + 3);
        const uint32_t st = sb + 32768 + (kt & 3) * FSTG;

        float sc[2][8][4];
#pragma unroll
        for (int mt = 0; mt < 2; mt++)
#pragma unroll
            for (int i = 0; i < 8; i++)
#pragma unroll
                for (int j = 0; j < 4; j++) sc[mt][i][j] = 0.f;

#pragma unroll
        for (int kk = 0; kk < 4; kk++) {
            const uint32_t swA = (uint32_t)(((kk * 2 + cA) ^ swz) << 4);
            const uint32_t swB = (uint32_t)(((kk * 2 + cB) ^ swz) << 4);
            uint32_t aq[2][4];
            ldm4(sb + aoff[0] + swA, aq[0]);
            ldm4(sb + aoff[1] + swA, aq[1]);
#pragma unroll
            for (int nt = 0; nt < 4; nt++) {
                uint32_t kh[4];
                ldm4(st + boff[nt] + swB, kh);
#pragma unroll
                for (int mt = 0; mt < 2; mt++)
#pragma unroll
                    for (int h = 0; h < 2; h++)
                        mma_f16(sc[mt][nt * 2 + h], aq[mt], &kh[h * 2]);
            }
        }

#pragma unroll
        for (int mt = 0; mt < 2; mt++)
#pragma unroll
            for (int p = 0; p < 2; p++) {
                float mx = -1e30f;
#pragma unroll
                for (int ng = 0; ng < 8; ng++)
                    mx = fmaxf(mx, fmaxf(sc[mt][ng][2 * p], sc[mt][ng][2 * p + 1]));
                mx = fmaxf(mx, __shfl_xor_sync(0xffffffffu, mx, 1));
                mx = fmaxf(mx, __shfl_xor_sync(0xffffffffu, mx, 2));
                const float mnew = fmaxf(m_r[mt][p], mx);
                const float f = exp2f(m_r[mt][p] - mnew);
                m_r[mt][p] = mnew;
                float rs = 0.f;
#pragma unroll
                for (int ng = 0; ng < 8; ng++) {
                    sc[mt][ng][2 * p]     = exp2f(sc[mt][ng][2 * p] - mnew);
                    sc[mt][ng][2 * p + 1] = exp2f(sc[mt][ng][2 * p + 1] - mnew);
                    rs += sc[mt][ng][2 * p] + sc[mt][ng][2 * p + 1];
                }
                rs += __shfl_xor_sync(0xffffffffu, rs, 1);
                rs += __shfl_xor_sync(0xffffffffu, rs, 2);
                l_r[mt][p] = l_r[mt][p] * f + rs;
#pragma unroll
                for (int dt = 0; dt < 8; dt++) {
                    oc[mt][dt][2 * p] *= f;
                    oc[mt][dt][2 * p + 1] *= f;
                }
            }

        // ---- O += P V : V via ldmatrix.trans on [s][d] rows ----
#pragma unroll
        for (int kk = 0; kk < 4; kk++) {
            uint32_t ph[2][4];
#pragma unroll
            for (int mt = 0; mt < 2; mt++)
#pragma unroll
                for (int u = 0; u < 2; u++) {
                    const int ng = 2 * kk + u;
#pragma unroll
                    for (int v = 0; v < 2; v++) {
                        __half2 hq = __floats2half2_rn(sc[mt][ng][2 * v],
                                                       sc[mt][ng][2 * v + 1]);
                        ph[mt][u * 2 + v] = *(uint32_t*)&hq;
                    }
                }
            const int s = kk * 16 + vs;                    // V row 0..63
            const uint32_t vrow = (uint32_t)(8192 + s * 128);
            const int sx = s & 7;
#pragma unroll
            for (int nt = 0; nt < 4; nt++) {
                const uint32_t addr = st + vrow +
                    (uint32_t)((((nt * 2 + vd) ^ sx)) << 4);
                uint32_t vh[4];
                ldm4t(addr, vh);
#pragma unroll
                for (int mt = 0; mt < 2; mt++)
#pragma unroll
                    for (int h2 = 0; h2 < 2; h2++)
                        mma_f16(oc[mt][nt * 2 + h2], ph[mt], &vh[h2 * 2]);
            }
        }
    }

    // ---- epilogue ----
#pragma unroll
    for (int mt = 0; mt < 2; mt++)
#pragma unroll
        for (int p = 0; p < 2; p++) {
            const int n = q0 + wid * 32 + mt * 16 + (lane >> 2) + 8 * p;
            const float inv = 1.f / l_r[mt][p];
#pragma unroll
            for (int dt = 0; dt < 8; dt++) {
                const int d = dt * 8 + 2 * (lane & 3);
                const size_t oi = ((size_t)(bb * N_ + n)) * C_ + hh * D_ + d;
                *(__half2*)&outs[oi] = __floats2half2_rn(
                    oc[mt][dt][2 * p] * inv, oc[mt][dt][2 * p + 1] * inv);
            }
        }
}

// =====================================================================
extern "C" void kernel_launch(void* const* d_in, const int* in_sizes, int n_in,
                              void* d_out, int out_size)
{
    const float* x      = (const float*)d_in[0];
    const float* cosd   = (const float*)d_in[1];
    const float* sind   = (const float*)d_in[2];
    const float* w_qkv  = (const float*)d_in[3];
    const float* w_proj = (const float*)d_in[4];
    const float* q_gam  = (const float*)d_in[5];
    const float* k_gam  = (const float*)d_in[6];
    float* out = (float*)d_out;

    __half *p_xh = nullptr, *p_wqkvh = nullptr, *p_atth = nullptr, *p_wprojh = nullptr;
    cudaGetSymbolAddress((void**)&p_xh, g_xh);
    cudaGetSymbolAddress((void**)&p_wqkvh, g_wqkvh);
    cudaGetSymbolAddress((void**)&p_atth, g_atth);
    cudaGetSymbolAddress((void**)&p_wprojh, g_wprojh);

    cudaFuncSetAttribute(gemm1_mma,
                         cudaFuncAttributeMaxDynamicSharedMemorySize, GSMEM1);
    cudaFuncSetAttribute(flash_mma,
                         cudaFuncAttributeMaxDynamicSharedMemorySize, FLASH_SMEM);

    // 1) fused fp32->fp16 split of x, w_qkv, w_proj (one launch)
    const size_t total = NX_ + NWQ_ + NWP_;
    splitall_kernel<<<(int)((total / 4 + 255) / 256), 256>>>(x, w_qkv, w_proj);

    // 2) QKV projection + fused RMSNorm/RoPE/layout epilogue
    gemm1_mma<<<dim3(3 * C_ / 256, BN_ / 128), 256, GSMEM1>>>(
        p_xh, p_wqkvh, nullptr, 3 * C_, C_, 1, cosd, sind, q_gam, k_gam);

    // 3) flash attention (V via ldmatrix.trans, no transpose kernel)
    flash_mma<<<dim3(N_ / 256, BH_), 256, FLASH_SMEM>>>(p_atth);

    // 4) output projection (plain fp32 epilogue)
    gemm1_mma<<<dim3(C_ / 256, BN_ / 128), 256, GSMEM1>>>(
        p_atth, p_wprojh, out, C_, C_, 0, nullptr, nullptr, nullptr, nullptr);
}